// round 3
// baseline (speedup 1.0000x reference)
#include <cuda_runtime.h>
#include <math.h>

#define B_  4
#define S_  2048
#define D_  1024
#define H_  16
#define DH_ 64
#define M_  (B_*S_)          // 8192 rows

// ---------------- scratch (no allocations allowed) ----------------
__device__ float g_q[(size_t)B_*H_*S_*DH_];    // [B,H,S,DH]
__device__ float g_k[(size_t)B_*H_*S_*DH_];
__device__ float g_v[(size_t)B_*H_*S_*DH_];
__device__ float g_ctx[(size_t)M_*D_];         // merged heads [M, D]
__device__ float g_res[(size_t)M_*D_];         // pre-layernorm

// =================================================================
// QKV GEMM: y = x @ W, W in {W_Q,W_K,W_V} by blockIdx.y, scatter to
// [B,H,S,DH]. Tiles: BM=BN=64, BK=16, 256 thr, 4x4 per thread.
// =================================================================
__global__ __launch_bounds__(256) void qkv_gemm(
    const float* __restrict__ x,
    const float* __restrict__ wq,
    const float* __restrict__ wk,
    const float* __restrict__ wv)
{
    __shared__ float As[16*68];   // [k][m] (transposed)
    __shared__ float Bs[16*68];   // [k][n]

    const int tid = threadIdx.x;
    const int tx = tid & 15, ty = tid >> 4;
    const int m0 = blockIdx.x * 64;
    const int ng = blockIdx.y * 64;       // 0..3071
    const int which = ng >> 10;           // 0=Q 1=K 2=V
    const int n0 = ng & 1023;
    const float* __restrict__ W = (which == 0) ? wq : (which == 1) ? wk : wv;
    float* __restrict__ outp     = (which == 0) ? g_q : (which == 1) ? g_k : g_v;

    const int arow = tid >> 2,  ac4 = (tid & 3) << 2;   // 64 rows x 4 float4-cols
    const int brow = tid >> 4,  bc4 = (tid & 15) << 2;  // 16 rows x 16 float4-cols

    float acc[4][4] = {};

    for (int k0 = 0; k0 < D_; k0 += 16) {
        float4 av = *(const float4*)(x + (size_t)(m0 + arow) * D_ + k0 + ac4);
        As[(ac4 + 0) * 68 + arow] = av.x;
        As[(ac4 + 1) * 68 + arow] = av.y;
        As[(ac4 + 2) * 68 + arow] = av.z;
        As[(ac4 + 3) * 68 + arow] = av.w;
        float4 bv = *(const float4*)(W + (size_t)(k0 + brow) * D_ + n0 + bc4);
        *(float4*)(Bs + brow * 68 + bc4) = bv;
        __syncthreads();
#pragma unroll
        for (int k = 0; k < 16; ++k) {
            float4 a4 = *(const float4*)(As + k * 68 + ty * 4);
            float4 b4 = *(const float4*)(Bs + k * 68 + tx * 4);
            float a[4] = {a4.x, a4.y, a4.z, a4.w};
            float b[4] = {b4.x, b4.y, b4.z, b4.w};
#pragma unroll
            for (int i = 0; i < 4; i++)
#pragma unroll
                for (int j = 0; j < 4; j++)
                    acc[i][j] = fmaf(a[i], b[j], acc[i][j]);
        }
        __syncthreads();
    }

#pragma unroll
    for (int i = 0; i < 4; i++) {
        int m = m0 + ty * 4 + i;
        int b = m >> 11, s = m & (S_ - 1);
#pragma unroll
        for (int j = 0; j < 4; j++) {
            int n = n0 + tx * 4 + j;
            int h = n >> 6, d = n & 63;
            outp[((size_t)(b * H_ + h) * S_ + s) * DH_ + d] = acc[i][j];
        }
    }
}

// =================================================================
// Flash attention (fp32, causal). One block = 64 queries of one (b,h).
// Smem layouts chosen for conflict-free float4 reads in both GEMMs:
//   Qt[d][q], Kt[d][key]  (rank-1 over d for S = Q K^T)
//   Pt[key][q], Vs[key][d] (rank-1 over key for O += P V)
// =================================================================
__global__ __launch_bounds__(256, 2) void attn_kernel()
{
    extern __shared__ float sm[];
    float* Qt = sm;                 // 64 x 68
    float* Kt = sm + 64 * 68;       // 64 x 68
    float* Vs = sm + 2 * 64 * 68;   // 64 x 68
    float* Pt = sm + 3 * 64 * 68;   // 64 x 68

    const int tid = threadIdx.x;
    const int tx = tid & 15, ty = tid >> 4;
    const int qt = blockIdx.x;
    const int bh = blockIdx.y;
    const int q0 = qt * 64;

    const float* __restrict__ Qg = g_q + (size_t)bh * S_ * DH_;
    const float* __restrict__ Kg = g_k + (size_t)bh * S_ * DH_;
    const float* __restrict__ Vg = g_v + (size_t)bh * S_ * DH_;

    // load Q tile transposed + pre-scaled by 1/sqrt(64)
#pragma unroll
    for (int t = 0; t < 4; ++t) {
        int idx = tid + t * 256;
        int r = idx >> 4, c4 = (idx & 15) << 2;
        float4 v = *(const float4*)(Qg + (size_t)(q0 + r) * DH_ + c4);
        Qt[(c4 + 0) * 68 + r] = v.x * 0.125f;
        Qt[(c4 + 1) * 68 + r] = v.y * 0.125f;
        Qt[(c4 + 2) * 68 + r] = v.z * 0.125f;
        Qt[(c4 + 3) * 68 + r] = v.w * 0.125f;
    }

    float acc[4][4] = {};
    float mrow[4] = {-1e30f, -1e30f, -1e30f, -1e30f};
    float lrow[4] = {};

    for (int kt = 0; kt <= qt; ++kt) {
        const int k0 = kt * 64;
#pragma unroll
        for (int t = 0; t < 4; ++t) {
            int idx = tid + t * 256;
            int r = idx >> 4, c4 = (idx & 15) << 2;
            float4 kv = *(const float4*)(Kg + (size_t)(k0 + r) * DH_ + c4);
            Kt[(c4 + 0) * 68 + r] = kv.x;
            Kt[(c4 + 1) * 68 + r] = kv.y;
            Kt[(c4 + 2) * 68 + r] = kv.z;
            Kt[(c4 + 3) * 68 + r] = kv.w;
            float4 vv = *(const float4*)(Vg + (size_t)(k0 + r) * DH_ + c4);
            *(float4*)(Vs + r * 68 + c4) = vv;
        }
        __syncthreads();

        // S = Q K^T  (rows i = queries ty*4+i, cols j = keys tx*4+j)
        float sv[4][4] = {};
#pragma unroll
        for (int d = 0; d < 64; ++d) {
            float4 qa = *(const float4*)(Qt + d * 68 + ty * 4);
            float4 kb = *(const float4*)(Kt + d * 68 + tx * 4);
            float a[4] = {qa.x, qa.y, qa.z, qa.w};
            float b[4] = {kb.x, kb.y, kb.z, kb.w};
#pragma unroll
            for (int i = 0; i < 4; i++)
#pragma unroll
                for (int j = 0; j < 4; j++)
                    sv[i][j] = fmaf(a[i], b[j], sv[i][j]);
        }

        if (kt == qt) {
#pragma unroll
            for (int i = 0; i < 4; i++)
#pragma unroll
                for (int j = 0; j < 4; j++)
                    if (tx * 4 + j > ty * 4 + i) sv[i][j] = -1e30f;
        }

        // online softmax; row stats shared by 16 lanes (same ty) in a warp half
#pragma unroll
        for (int i = 0; i < 4; i++) {
            float tm = fmaxf(fmaxf(sv[i][0], sv[i][1]), fmaxf(sv[i][2], sv[i][3]));
            tm = fmaxf(tm, __shfl_xor_sync(0xffffffffu, tm, 1));
            tm = fmaxf(tm, __shfl_xor_sync(0xffffffffu, tm, 2));
            tm = fmaxf(tm, __shfl_xor_sync(0xffffffffu, tm, 4));
            tm = fmaxf(tm, __shfl_xor_sync(0xffffffffu, tm, 8));
            float mn = fmaxf(mrow[i], tm);
            float alpha = __expf(mrow[i] - mn);
            mrow[i] = mn;
            float psum = 0.f;
#pragma unroll
            for (int j = 0; j < 4; j++) {
                float p = __expf(sv[i][j] - mn);
                Pt[(tx * 4 + j) * 68 + ty * 4 + i] = p;   // transposed store
                psum += p;
            }
            psum += __shfl_xor_sync(0xffffffffu, psum, 1);
            psum += __shfl_xor_sync(0xffffffffu, psum, 2);
            psum += __shfl_xor_sync(0xffffffffu, psum, 4);
            psum += __shfl_xor_sync(0xffffffffu, psum, 8);
            lrow[i] = lrow[i] * alpha + psum;
#pragma unroll
            for (int j = 0; j < 4; j++) acc[i][j] *= alpha;
        }
        __syncthreads();

        // O += P V   (rows i = queries, cols j = dh tx*4+j)
#pragma unroll
        for (int c = 0; c < 64; ++c) {
            float4 pa = *(const float4*)(Pt + c * 68 + ty * 4);
            float4 vb = *(const float4*)(Vs + c * 68 + tx * 4);
            float a[4] = {pa.x, pa.y, pa.z, pa.w};
            float b[4] = {vb.x, vb.y, vb.z, vb.w};
#pragma unroll
            for (int i = 0; i < 4; i++)
#pragma unroll
                for (int j = 0; j < 4; j++)
                    acc[i][j] = fmaf(a[i], b[j], acc[i][j]);
        }
        __syncthreads();
    }

    const int b = bh >> 4, h = bh & 15;
#pragma unroll
    for (int i = 0; i < 4; i++) {
        float inv = 1.0f / lrow[i];
        size_t grow = (size_t)(b * S_ + q0 + ty * 4 + i) * D_ + h * 64;
#pragma unroll
        for (int j = 0; j < 4; j++)
            g_ctx[grow + tx * 4 + j] = acc[i][j] * inv;
    }
}

// =================================================================
// Output projection + residual: g_res = g_ctx @ W_O + x
// =================================================================
__global__ __launch_bounds__(256) void proj_gemm(
    const float* __restrict__ x,
    const float* __restrict__ wo)
{
    __shared__ float As[16*68];
    __shared__ float Bs[16*68];

    const int tid = threadIdx.x;
    const int tx = tid & 15, ty = tid >> 4;
    const int m0 = blockIdx.x * 64;
    const int n0 = blockIdx.y * 64;

    const int arow = tid >> 2,  ac4 = (tid & 3) << 2;
    const int brow = tid >> 4,  bc4 = (tid & 15) << 2;

    float acc[4][4] = {};

    for (int k0 = 0; k0 < D_; k0 += 16) {
        float4 av = *(const float4*)(g_ctx + (size_t)(m0 + arow) * D_ + k0 + ac4);
        As[(ac4 + 0) * 68 + arow] = av.x;
        As[(ac4 + 1) * 68 + arow] = av.y;
        As[(ac4 + 2) * 68 + arow] = av.z;
        As[(ac4 + 3) * 68 + arow] = av.w;
        float4 bv = *(const float4*)(wo + (size_t)(k0 + brow) * D_ + n0 + bc4);
        *(float4*)(Bs + brow * 68 + bc4) = bv;
        __syncthreads();
#pragma unroll
        for (int k = 0; k < 16; ++k) {
            float4 a4 = *(const float4*)(As + k * 68 + ty * 4);
            float4 b4 = *(const float4*)(Bs + k * 68 + tx * 4);
            float a[4] = {a4.x, a4.y, a4.z, a4.w};
            float b[4] = {b4.x, b4.y, b4.z, b4.w};
#pragma unroll
            for (int i = 0; i < 4; i++)
#pragma unroll
                for (int j = 0; j < 4; j++)
                    acc[i][j] = fmaf(a[i], b[j], acc[i][j]);
        }
        __syncthreads();
    }

#pragma unroll
    for (int i = 0; i < 4; i++) {
        size_t m = m0 + ty * 4 + i;
#pragma unroll
        for (int j = 0; j < 4; j++) {
            size_t n = n0 + tx * 4 + j;
            g_res[m * D_ + n] = acc[i][j] + x[m * D_ + n];
        }
    }
}

// =================================================================
// LayerNorm over last dim (1024): one block per row, 256 threads x 4
// =================================================================
__global__ __launch_bounds__(256) void ln_kernel(
    const float* __restrict__ gamma,
    const float* __restrict__ beta,
    float* __restrict__ out)
{
    __shared__ float r1[256];
    __shared__ float r2[256];
    const int row = blockIdx.x;
    const int t = threadIdx.x;
    const float* rp = g_res + (size_t)row * D_;

    float4 v = *(const float4*)(rp + t * 4);
    float s = v.x + v.y + v.z + v.w;
    float q = v.x * v.x + v.y * v.y + v.z * v.z + v.w * v.w;
    r1[t] = s; r2[t] = q;
    __syncthreads();
    for (int o = 128; o > 0; o >>= 1) {
        if (t < o) { r1[t] += r1[t + o]; r2[t] += r2[t + o]; }
        __syncthreads();
    }
    float mu  = r1[0] * (1.0f / 1024.0f);
    float var = r2[0] * (1.0f / 1024.0f) - mu * mu;
    float rstd = rsqrtf(var + 1e-5f);

    float4 g  = *(const float4*)(gamma + t * 4);
    float4 bt = *(const float4*)(beta  + t * 4);
    float4 o4;
    o4.x = (v.x - mu) * rstd * g.x + bt.x;
    o4.y = (v.y - mu) * rstd * g.y + bt.y;
    o4.z = (v.z - mu) * rstd * g.z + bt.z;
    o4.w = (v.w - mu) * rstd * g.w + bt.w;
    *(float4*)(out + (size_t)row * D_ + t * 4) = o4;
}

// =================================================================
extern "C" void kernel_launch(void* const* d_in, const int* in_sizes, int n_in,
                              void* d_out, int out_size)
{
    const float* x     = (const float*)d_in[0];
    const float* wq    = (const float*)d_in[1];
    const float* wk    = (const float*)d_in[2];
    const float* wv    = (const float*)d_in[3];
    const float* wo    = (const float*)d_in[4];
    const float* gamma = (const float*)d_in[5];
    const float* beta  = (const float*)d_in[6];
    float* out = (float*)d_out;

    // 4 x 64x68 fp32 tiles = 69632 B dynamic smem (> 48KB static limit)
    cudaFuncSetAttribute(attn_kernel,
                         cudaFuncAttributeMaxDynamicSharedMemorySize, 69632);

    qkv_gemm<<<dim3(M_ / 64, 48), 256>>>(x, wq, wk, wv);
    attn_kernel<<<dim3(S_ / 64, B_ * H_), 256, 69632>>>();
    proj_gemm<<<dim3(M_ / 64, D_ / 64), 256>>>(x, wo);
    ln_kernel<<<M_, 256>>>(gamma, beta, out);
}

// round 4
// speedup vs baseline: 1.1667x; 1.1667x over previous
#include <cuda_runtime.h>
#include <math.h>

#define B_  4
#define S_  2048
#define D_  1024
#define H_  16
#define DH_ 64
#define M_  (B_*S_)          // 8192 rows

typedef unsigned long long u64;

// ---------------- f32x2 packed helpers (FFMA2 path) ----------------
__device__ __forceinline__ u64 pack2(float x, float y) {
    u64 r; asm("mov.b64 %0, {%1, %2};" : "=l"(r) : "f"(x), "f"(y)); return r;
}
__device__ __forceinline__ u64 dup2(float x) {
    u64 r; asm("mov.b64 %0, {%1, %1};" : "=l"(r) : "f"(x)); return r;
}
__device__ __forceinline__ void unpack2(u64 v, float& x, float& y) {
    asm("mov.b64 {%0, %1}, %2;" : "=f"(x), "=f"(y) : "l"(v));
}
__device__ __forceinline__ u64 ffma2(u64 a, u64 b, u64 c) {
    u64 d; asm("fma.rn.f32x2 %0, %1, %2, %3;" : "=l"(d) : "l"(a), "l"(b), "l"(c)); return d;
}
__device__ __forceinline__ u64 fmul2(u64 a, u64 b) {
    u64 d; asm("mul.rn.f32x2 %0, %1, %2;" : "=l"(d) : "l"(a), "l"(b)); return d;
}

// ---------------- scratch (no allocations allowed) ----------------
__device__ float g_q[(size_t)B_*H_*S_*DH_];    // [B,H,S,DH]
__device__ float g_k[(size_t)B_*H_*S_*DH_];
__device__ float g_v[(size_t)B_*H_*S_*DH_];
__device__ float g_ctx[(size_t)M_*D_];         // merged heads [M, D]
__device__ float g_res[(size_t)M_*D_];         // pre-layernorm

// =================================================================
// Shared 128x128-tile fp32 GEMM core (BK=16, 256 thr, 8x8/thread,
// FFMA2 packed over column pairs). A is m-major [*, D_], W is [D_, *].
// acc2[i][jp]: rows i<4 -> ty*4+i, i>=4 -> 64+ty*4+(i-4);
//             col pairs jp<2 -> tx*4+2jp, jp>=2 -> 64+tx*4+2(jp-2).
// =================================================================
#define GSTR 132   // smem row stride in floats (16B-aligned: 528B)

__device__ __forceinline__ void gemm_tile_128(
    const float* __restrict__ A, const float* __restrict__ W,
    int m0, int n0, float* As, float* Bs, u64 acc2[8][4])
{
    const int tid = threadIdx.x;
    const int tx = tid & 15, ty = tid >> 4;
    const int arow = tid >> 1, akc = (tid & 1) * 8;     // A: 128 rows x 16 k
    const int wr = tid >> 4,  wc = (tid & 15) * 4;      // W: 16 rows x 128 cols

    for (int k0 = 0; k0 < D_; k0 += 16) {
        // A tile -> As transposed [k][m]
        float4 a0 = *(const float4*)(A + (size_t)(m0 + arow) * D_ + k0 + akc);
        float4 a1 = *(const float4*)(A + (size_t)(m0 + arow) * D_ + k0 + akc + 4);
        As[(akc + 0) * GSTR + arow] = a0.x;
        As[(akc + 1) * GSTR + arow] = a0.y;
        As[(akc + 2) * GSTR + arow] = a0.z;
        As[(akc + 3) * GSTR + arow] = a0.w;
        As[(akc + 4) * GSTR + arow] = a1.x;
        As[(akc + 5) * GSTR + arow] = a1.y;
        As[(akc + 6) * GSTR + arow] = a1.z;
        As[(akc + 7) * GSTR + arow] = a1.w;
        // W tile -> Bs [k][n]
        *(float4*)(Bs + wr * GSTR + wc) =
            *(const float4*)(W + (size_t)(k0 + wr) * D_ + n0 + wc);
        *(float4*)(Bs + wr * GSTR + wc + 64) =
            *(const float4*)(W + (size_t)(k0 + wr) * D_ + n0 + wc + 64);
        __syncthreads();

#pragma unroll
        for (int k = 0; k < 16; ++k) {
            float4 al = *(const float4*)(As + k * GSTR + ty * 4);
            float4 ah = *(const float4*)(As + k * GSTR + 64 + ty * 4);
            float4 bl = *(const float4*)(Bs + k * GSTR + tx * 4);
            float4 bh = *(const float4*)(Bs + k * GSTR + 64 + tx * 4);
            u64 bb[4] = { pack2(bl.x, bl.y), pack2(bl.z, bl.w),
                          pack2(bh.x, bh.y), pack2(bh.z, bh.w) };
            float av[8] = { al.x, al.y, al.z, al.w, ah.x, ah.y, ah.z, ah.w };
#pragma unroll
            for (int i = 0; i < 8; i++) {
                u64 ad = dup2(av[i]);
#pragma unroll
                for (int jp = 0; jp < 4; jp++)
                    acc2[i][jp] = ffma2(ad, bb[jp], acc2[i][jp]);
            }
        }
        __syncthreads();
    }
}

// =================================================================
// QKV GEMM: y = x @ {W_Q,W_K,W_V}, scatter to [B,H,S,DH]
// =================================================================
__global__ __launch_bounds__(256) void qkv_gemm(
    const float* __restrict__ x,
    const float* __restrict__ wq,
    const float* __restrict__ wk,
    const float* __restrict__ wv)
{
    __shared__ float As[16 * GSTR];
    __shared__ float Bs[16 * GSTR];

    const int tid = threadIdx.x;
    const int tx = tid & 15, ty = tid >> 4;
    const int m0 = blockIdx.x * 128;
    const int ng = blockIdx.y * 128;      // 0..3071
    const int which = ng >> 10;           // 0=Q 1=K 2=V
    const int n0 = ng & 1023;
    const float* __restrict__ W = (which == 0) ? wq : (which == 1) ? wk : wv;
    float* __restrict__ outp     = (which == 0) ? g_q : (which == 1) ? g_k : g_v;

    u64 acc2[8][4] = {};
    gemm_tile_128(x, W, m0, n0, As, Bs, acc2);

#pragma unroll
    for (int i = 0; i < 8; i++) {
        int m = m0 + ((i < 4) ? (ty * 4 + i) : (64 + ty * 4 + i - 4));
        int b = m >> 11, s = m & (S_ - 1);
#pragma unroll
        for (int jp = 0; jp < 4; jp++) {
            int n = n0 + ((jp < 2) ? (tx * 4 + 2 * jp) : (64 + tx * 4 + 2 * (jp - 2)));
            int h = n >> 6, d = n & 63;
            float2 f; unpack2(acc2[i][jp], f.x, f.y);
            *(float2*)(outp + ((size_t)(b * H_ + h) * S_ + s) * DH_ + d) = f;
        }
    }
}

// =================================================================
// Output projection + residual: g_res = g_ctx @ W_O + x
// =================================================================
__global__ __launch_bounds__(256) void proj_gemm(
    const float* __restrict__ x,
    const float* __restrict__ wo)
{
    __shared__ float As[16 * GSTR];
    __shared__ float Bs[16 * GSTR];

    const int tid = threadIdx.x;
    const int tx = tid & 15, ty = tid >> 4;
    const int m0 = blockIdx.x * 128;
    const int n0 = blockIdx.y * 128;

    u64 acc2[8][4] = {};
    gemm_tile_128(g_ctx, wo, m0, n0, As, Bs, acc2);

#pragma unroll
    for (int i = 0; i < 8; i++) {
        size_t m = m0 + ((i < 4) ? (ty * 4 + i) : (64 + ty * 4 + i - 4));
#pragma unroll
        for (int jp = 0; jp < 4; jp++) {
            size_t n = n0 + ((jp < 2) ? (tx * 4 + 2 * jp) : (64 + tx * 4 + 2 * (jp - 2)));
            float2 f; unpack2(acc2[i][jp], f.x, f.y);
            float2 xr = *(const float2*)(x + m * D_ + n);
            f.x += xr.x; f.y += xr.y;
            *(float2*)(g_res + m * D_ + n) = f;
        }
    }
}

// =================================================================
// Flash attention (fp32 FFMA2, causal). One block = 64 queries/(b,h).
//   Qt[d][q], Kt[d][key]  (rank-1 over d for S = Q K^T)
//   Pt[key][q], Vs[key][d] (rank-1 over key for O += P V)
// =================================================================
__global__ __launch_bounds__(256, 2) void attn_kernel()
{
    extern __shared__ float sm[];
    float* Qt = sm;                 // 64 x 68
    float* Kt = sm + 64 * 68;
    float* Vs = sm + 2 * 64 * 68;
    float* Pt = sm + 3 * 64 * 68;

    const int tid = threadIdx.x;
    const int tx = tid & 15, ty = tid >> 4;
    const int qt = blockIdx.x;
    const int bh = blockIdx.y;
    const int q0 = qt * 64;

    const float* __restrict__ Qg = g_q + (size_t)bh * S_ * DH_;
    const float* __restrict__ Kg = g_k + (size_t)bh * S_ * DH_;
    const float* __restrict__ Vg = g_v + (size_t)bh * S_ * DH_;

    // load Q tile transposed + pre-scaled by 1/sqrt(64)
#pragma unroll
    for (int t = 0; t < 4; ++t) {
        int idx = tid + t * 256;
        int r = idx >> 4, c4 = (idx & 15) << 2;
        float4 v = *(const float4*)(Qg + (size_t)(q0 + r) * DH_ + c4);
        Qt[(c4 + 0) * 68 + r] = v.x * 0.125f;
        Qt[(c4 + 1) * 68 + r] = v.y * 0.125f;
        Qt[(c4 + 2) * 68 + r] = v.z * 0.125f;
        Qt[(c4 + 3) * 68 + r] = v.w * 0.125f;
    }

    u64 acc2[4][2] = {};                         // cols tx*4+{0,1},{2,3}
    float mrow[4] = {-1e30f, -1e30f, -1e30f, -1e30f};
    float lrow[4] = {};

    for (int kt = 0; kt <= qt; ++kt) {
        const int k0 = kt * 64;
#pragma unroll
        for (int t = 0; t < 4; ++t) {
            int idx = tid + t * 256;
            int r = idx >> 4, c4 = (idx & 15) << 2;
            float4 kv = *(const float4*)(Kg + (size_t)(k0 + r) * DH_ + c4);
            Kt[(c4 + 0) * 68 + r] = kv.x;
            Kt[(c4 + 1) * 68 + r] = kv.y;
            Kt[(c4 + 2) * 68 + r] = kv.z;
            Kt[(c4 + 3) * 68 + r] = kv.w;
            *(float4*)(Vs + r * 68 + c4) =
                *(const float4*)(Vg + (size_t)(k0 + r) * DH_ + c4);
        }
        __syncthreads();

        // S = Q K^T  (packed over key pairs)
        u64 sv2[4][2] = {};
#pragma unroll
        for (int d = 0; d < 64; ++d) {
            float4 qa = *(const float4*)(Qt + d * 68 + ty * 4);
            float4 kb = *(const float4*)(Kt + d * 68 + tx * 4);
            u64 b0 = pack2(kb.x, kb.y), b1 = pack2(kb.z, kb.w);
            float av[4] = { qa.x, qa.y, qa.z, qa.w };
#pragma unroll
            for (int i = 0; i < 4; i++) {
                u64 ad = dup2(av[i]);
                sv2[i][0] = ffma2(ad, b0, sv2[i][0]);
                sv2[i][1] = ffma2(ad, b1, sv2[i][1]);
            }
        }

        float sv[4][4];
#pragma unroll
        for (int i = 0; i < 4; i++) {
            unpack2(sv2[i][0], sv[i][0], sv[i][1]);
            unpack2(sv2[i][1], sv[i][2], sv[i][3]);
        }

        if (kt == qt) {
#pragma unroll
            for (int i = 0; i < 4; i++)
#pragma unroll
                for (int j = 0; j < 4; j++)
                    if (tx * 4 + j > ty * 4 + i) sv[i][j] = -1e30f;
        }

        // online softmax; row stats shared by 16 lanes (same ty)
#pragma unroll
        for (int i = 0; i < 4; i++) {
            float tm = fmaxf(fmaxf(sv[i][0], sv[i][1]), fmaxf(sv[i][2], sv[i][3]));
            tm = fmaxf(tm, __shfl_xor_sync(0xffffffffu, tm, 1));
            tm = fmaxf(tm, __shfl_xor_sync(0xffffffffu, tm, 2));
            tm = fmaxf(tm, __shfl_xor_sync(0xffffffffu, tm, 4));
            tm = fmaxf(tm, __shfl_xor_sync(0xffffffffu, tm, 8));
            float mn = fmaxf(mrow[i], tm);
            float alpha = __expf(mrow[i] - mn);
            mrow[i] = mn;
            float psum = 0.f;
#pragma unroll
            for (int j = 0; j < 4; j++) {
                float p = __expf(sv[i][j] - mn);
                Pt[(tx * 4 + j) * 68 + ty * 4 + i] = p;   // transposed store
                psum += p;
            }
            psum += __shfl_xor_sync(0xffffffffu, psum, 1);
            psum += __shfl_xor_sync(0xffffffffu, psum, 2);
            psum += __shfl_xor_sync(0xffffffffu, psum, 4);
            psum += __shfl_xor_sync(0xffffffffu, psum, 8);
            lrow[i] = lrow[i] * alpha + psum;
            u64 al2 = dup2(alpha);
            acc2[i][0] = fmul2(acc2[i][0], al2);
            acc2[i][1] = fmul2(acc2[i][1], al2);
        }
        __syncthreads();

        // O += P V (packed over dh pairs)
#pragma unroll
        for (int c = 0; c < 64; ++c) {
            float4 pa = *(const float4*)(Pt + c * 68 + ty * 4);
            float4 vb = *(const float4*)(Vs + c * 68 + tx * 4);
            u64 b0 = pack2(vb.x, vb.y), b1 = pack2(vb.z, vb.w);
            float av[4] = { pa.x, pa.y, pa.z, pa.w };
#pragma unroll
            for (int i = 0; i < 4; i++) {
                u64 ad = dup2(av[i]);
                acc2[i][0] = ffma2(ad, b0, acc2[i][0]);
                acc2[i][1] = ffma2(ad, b1, acc2[i][1]);
            }
        }
        __syncthreads();
    }

    const int b = bh >> 4, h = bh & 15;
#pragma unroll
    for (int i = 0; i < 4; i++) {
        float inv = 1.0f / lrow[i];
        size_t grow = (size_t)(b * S_ + q0 + ty * 4 + i) * D_ + h * 64;
#pragma unroll
        for (int jp = 0; jp < 2; jp++) {
            float2 f; unpack2(acc2[i][jp], f.x, f.y);
            f.x *= inv; f.y *= inv;
            *(float2*)(g_ctx + grow + tx * 4 + jp * 2) = f;
        }
    }
}

// =================================================================
// LayerNorm over last dim (1024): warp-shuffle reduction, 1 sync
// =================================================================
__global__ __launch_bounds__(256) void ln_kernel(
    const float* __restrict__ gamma,
    const float* __restrict__ beta,
    float* __restrict__ out)
{
    __shared__ float ws[8], wq[8];
    const int row = blockIdx.x;
    const int t = threadIdx.x;
    const int lane = t & 31, w = t >> 5;
    const float* rp = g_res + (size_t)row * D_;

    float4 v = *(const float4*)(rp + t * 4);
    float s = v.x + v.y + v.z + v.w;
    float q = v.x * v.x + v.y * v.y + v.z * v.z + v.w * v.w;
#pragma unroll
    for (int o = 16; o > 0; o >>= 1) {
        s += __shfl_xor_sync(0xffffffffu, s, o);
        q += __shfl_xor_sync(0xffffffffu, q, o);
    }
    if (lane == 0) { ws[w] = s; wq[w] = q; }
    __syncthreads();
    float S = 0.f, Q = 0.f;
#pragma unroll
    for (int i = 0; i < 8; i++) { S += ws[i]; Q += wq[i]; }

    float mu  = S * (1.0f / 1024.0f);
    float var = Q * (1.0f / 1024.0f) - mu * mu;
    float rstd = rsqrtf(var + 1e-5f);

    float4 g  = *(const float4*)(gamma + t * 4);
    float4 bt = *(const float4*)(beta  + t * 4);
    float4 o4;
    o4.x = (v.x - mu) * rstd * g.x + bt.x;
    o4.y = (v.y - mu) * rstd * g.y + bt.y;
    o4.z = (v.z - mu) * rstd * g.z + bt.z;
    o4.w = (v.w - mu) * rstd * g.w + bt.w;
    *(float4*)(out + (size_t)row * D_ + t * 4) = o4;
}

// =================================================================
extern "C" void kernel_launch(void* const* d_in, const int* in_sizes, int n_in,
                              void* d_out, int out_size)
{
    const float* x     = (const float*)d_in[0];
    const float* wq    = (const float*)d_in[1];
    const float* wk    = (const float*)d_in[2];
    const float* wv    = (const float*)d_in[3];
    const float* wo    = (const float*)d_in[4];
    const float* gamma = (const float*)d_in[5];
    const float* beta  = (const float*)d_in[6];
    float* out = (float*)d_out;

    cudaFuncSetAttribute(attn_kernel,
                         cudaFuncAttributeMaxDynamicSharedMemorySize, 69632);

    qkv_gemm<<<dim3(M_ / 128, 24), 256>>>(x, wq, wk, wv);
    attn_kernel<<<dim3(S_ / 64, B_ * H_), 256, 69632>>>();
    proj_gemm<<<dim3(M_ / 128, D_ / 128), 256>>>(x, wo);
    ln_kernel<<<M_, 256>>>(gamma, beta, out);
}

// round 8
// speedup vs baseline: 1.5292x; 1.3107x over previous
#include <cuda_runtime.h>
#include <cuda_bf16.h>
#include <math.h>

#define B_  4
#define S_  2048
#define D_  1024
#define H_  16
#define DH_ 64
#define M_  (B_*S_)          // 8192 rows

typedef unsigned long long u64;
typedef unsigned int u32;

// ---------------- f32x2 packed helpers (attention SIMT path) ------
__device__ __forceinline__ u64 pack2(float x, float y) {
    u64 r; asm("mov.b64 %0, {%1, %2};" : "=l"(r) : "f"(x), "f"(y)); return r;
}
__device__ __forceinline__ u64 dup2(float x) {
    u64 r; asm("mov.b64 %0, {%1, %1};" : "=l"(r) : "f"(x)); return r;
}
__device__ __forceinline__ void unpack2(u64 v, float& x, float& y) {
    asm("mov.b64 {%0, %1}, %2;" : "=f"(x), "=f"(y) : "l"(v));
}
__device__ __forceinline__ u64 ffma2(u64 a, u64 b, u64 c) {
    u64 d; asm("fma.rn.f32x2 %0, %1, %2, %3;" : "=l"(d) : "l"(a), "l"(b), "l"(c)); return d;
}
__device__ __forceinline__ u64 fmul2(u64 a, u64 b) {
    u64 d; asm("mul.rn.f32x2 %0, %1, %2;" : "=l"(d) : "l"(a), "l"(b)); return d;
}

// ---------------- HMMA helpers (non-'a' baseline tensor path) -----
__device__ __forceinline__ u32 smem_u32(const void* p) {
    u32 a;
    asm("{ .reg .u64 t; cvta.to.shared.u64 t, %1; cvt.u32.u64 %0, t; }"
        : "=r"(a) : "l"(p));
    return a;
}
__device__ __forceinline__ void ldmx4(u32* r, u32 addr) {
    asm volatile("ldmatrix.sync.aligned.m8n8.x4.shared.b16 {%0,%1,%2,%3}, [%4];"
                 : "=r"(r[0]), "=r"(r[1]), "=r"(r[2]), "=r"(r[3]) : "r"(addr));
}
__device__ __forceinline__ void mma_bf16(float* c, const u32* a, u32 b0, u32 b1) {
    asm volatile(
        "mma.sync.aligned.m16n8k16.row.col.f32.bf16.bf16.f32 "
        "{%0,%1,%2,%3}, {%4,%5,%6,%7}, {%8,%9}, {%0,%1,%2,%3};"
        : "+f"(c[0]), "+f"(c[1]), "+f"(c[2]), "+f"(c[3])
        : "r"(a[0]), "r"(a[1]), "r"(a[2]), "r"(a[3]), "r"(b0), "r"(b1));
}

// ---------------- scratch (no allocations allowed) ----------------
__device__ float g_q[(size_t)B_*H_*S_*DH_];    // [B,H,S,DH]
__device__ float g_k[(size_t)B_*H_*S_*DH_];
__device__ float g_v[(size_t)B_*H_*S_*DH_];
__device__ float g_res[(size_t)M_*D_];         // pre-layernorm
__device__ __nv_bfloat16 g_x_hi[(size_t)M_*D_];
__device__ __nv_bfloat16 g_x_lo[(size_t)M_*D_];
__device__ __nv_bfloat16 g_wt_hi[(size_t)4096*1024];   // [n][k]: 0-3071 WQKV^T, 3072-4095 WO^T
__device__ __nv_bfloat16 g_wt_lo[(size_t)4096*1024];
__device__ __nv_bfloat16 g_cx_hi[(size_t)M_*D_];       // ctx split [m][k]
__device__ __nv_bfloat16 g_cx_lo[(size_t)M_*D_];

// =================================================================
// Prep: split x into bf16 hi/lo
// =================================================================
__global__ __launch_bounds__(256) void split_x(const float* __restrict__ x)
{
    size_t i = (size_t)blockIdx.x * 1024 + threadIdx.x * 4;
    float4 v = *(const float4*)(x + i);
    __nv_bfloat16 h0 = __float2bfloat16(v.x), h1 = __float2bfloat16(v.y);
    __nv_bfloat16 h2 = __float2bfloat16(v.z), h3 = __float2bfloat16(v.w);
    __nv_bfloat162 a; a.x = h0; a.y = h1;
    __nv_bfloat162 b; b.x = h2; b.y = h3;
    *(__nv_bfloat162*)(g_x_hi + i)     = a;
    *(__nv_bfloat162*)(g_x_hi + i + 2) = b;
    a.x = __float2bfloat16(v.x - __bfloat162float(h0));
    a.y = __float2bfloat16(v.y - __bfloat162float(h1));
    b.x = __float2bfloat16(v.z - __bfloat162float(h2));
    b.y = __float2bfloat16(v.w - __bfloat162float(h3));
    *(__nv_bfloat162*)(g_x_lo + i)     = a;
    *(__nv_bfloat162*)(g_x_lo + i + 2) = b;
}

// =================================================================
// Prep: transpose W (k-major -> n-major) + split into bf16 hi/lo
// =================================================================
__global__ void wt_split(const float* __restrict__ wq, const float* __restrict__ wk,
                         const float* __restrict__ wv, const float* __restrict__ wo)
{
    __shared__ float tile[32][33];
    const int k0 = blockIdx.x * 32, n0 = blockIdx.y * 32;
    const int mat = n0 >> 10, c0 = n0 & 1023;
    const float* __restrict__ W = (mat == 0) ? wq : (mat == 1) ? wk : (mat == 2) ? wv : wo;
    const int tx = threadIdx.x, ty = threadIdx.y;
#pragma unroll
    for (int i = 0; i < 4; i++)
        tile[ty + i * 8][tx] = W[(size_t)(k0 + ty + i * 8) * 1024 + c0 + tx];
    __syncthreads();
#pragma unroll
    for (int i = 0; i < 4; i++) {
        int rr = ty + i * 8;
        float v = tile[tx][rr];
        __nv_bfloat16 h = __float2bfloat16(v);
        size_t o = (size_t)(n0 + rr) * 1024 + k0 + tx;
        g_wt_hi[o] = h;
        g_wt_lo[o] = __float2bfloat16(v - __bfloat162float(h));
    }
}

// =================================================================
// HMMA GEMM core: C(128x128 f32) = Ah@Bh^T + Ah@Bl^T + Al@Bh^T
// A [m][k] bf16 row-major, B [n][k] bf16 (col-major for mma.row.col).
// 256 thr = 8 warps (4m x 2n), warp tile 32x64, BK=32 (2 k16 steps).
// =================================================================
#define SK 40   // padded smem row stride in bf16 (80B: 8-row ldmatrix conflict-free)

__device__ __forceinline__ void ld_tile(const __nv_bfloat16* __restrict__ src,
                                        int row0, int k0,
                                        __nv_bfloat16* dst, int tid)
{
    const int row = tid >> 1, half = tid & 1;
    const uint4* s = (const uint4*)(src + (size_t)(row0 + row) * 1024 + k0 + half * 16);
    uint4* d = (uint4*)(dst + row * SK + half * 16);
    d[0] = s[0];
    d[1] = s[1];
}

__device__ __forceinline__ void hmma_core(
    const __nv_bfloat16* __restrict__ Ah, const __nv_bfloat16* __restrict__ Al,
    const __nv_bfloat16* __restrict__ Bh, const __nv_bfloat16* __restrict__ Bl,
    int m0, int n0row,
    __nv_bfloat16* sAh, __nv_bfloat16* sAl,
    __nv_bfloat16* sBh, __nv_bfloat16* sBl,
    float acc[2][8][4])
{
    const int tid = threadIdx.x;
    const int lane = tid & 31, wid = tid >> 5;
    const int wm = wid >> 1, wn = wid & 1;
    const int lrow = lane & 15, lcol = (lane >> 4) << 3;

    const u32 aHu = smem_u32(sAh), aLu = smem_u32(sAl);
    const u32 bHu = smem_u32(sBh), bLu = smem_u32(sBl);
    const u32 aoff = ((wm * 32 + lrow) * SK + lcol) * 2;
    const u32 boff = ((wn * 64 + lrow) * SK + lcol) * 2;

    for (int c = 0; c < 32; ++c) {
        const int k0 = c * 32;
        ld_tile(Ah, m0, k0, sAh, tid);
        ld_tile(Al, m0, k0, sAl, tid);
        ld_tile(Bh, n0row, k0, sBh, tid);
        ld_tile(Bl, n0row, k0, sBl, tid);
        __syncthreads();
#pragma unroll
        for (int ks = 0; ks < 2; ++ks) {
            const u32 kofs = ks * 32;          // 16 bf16 = 32 bytes
            u32 ah[2][4], al[2][4];
            ldmx4(ah[0], aHu + aoff + kofs);
            ldmx4(ah[1], aHu + aoff + 16 * SK * 2 + kofs);
            ldmx4(al[0], aLu + aoff + kofs);
            ldmx4(al[1], aLu + aoff + 16 * SK * 2 + kofs);
#pragma unroll
            for (int half = 0; half < 2; ++half) {
                const u32 hof = half * 32 * SK * 2;
                u32 bh[2][4], bl[2][4];
                ldmx4(bh[0], bHu + boff + hof + kofs);
                ldmx4(bh[1], bHu + boff + hof + 16 * SK * 2 + kofs);
                ldmx4(bl[0], bLu + boff + hof + kofs);
                ldmx4(bl[1], bLu + boff + hof + 16 * SK * 2 + kofs);
#pragma unroll
                for (int mi = 0; mi < 2; ++mi)
#pragma unroll
                    for (int jj = 0; jj < 4; ++jj) {
                        const int jb = jj >> 1, s = jj & 1;
                        float* cc = acc[mi][half * 4 + jj];
                        mma_bf16(cc, ah[mi], bh[jb][s], bh[jb][s + 2]);
                        mma_bf16(cc, ah[mi], bl[jb][s], bl[jb][s + 2]);
                        mma_bf16(cc, al[mi], bh[jb][s], bh[jb][s + 2]);
                    }
            }
        }
        __syncthreads();
    }
}

// =================================================================
// QKV GEMM (HMMA): scatter to g_q/g_k/g_v [B,H,S,DH] f32
// =================================================================
__global__ __launch_bounds__(256, 2) void qkv_hmma()
{
    __shared__ __align__(16) __nv_bfloat16 sAh[128 * SK];
    __shared__ __align__(16) __nv_bfloat16 sAl[128 * SK];
    __shared__ __align__(16) __nv_bfloat16 sBh[128 * SK];
    __shared__ __align__(16) __nv_bfloat16 sBl[128 * SK];

    const int m0 = blockIdx.x * 128;
    const int n0 = blockIdx.y * 128;          // 0..3071

    float acc[2][8][4] = {};
    hmma_core(g_x_hi, g_x_lo, g_wt_hi, g_wt_lo, m0, n0, sAh, sAl, sBh, sBl, acc);

    const int tid = threadIdx.x, lane = tid & 31, wid = tid >> 5;
    const int wm = wid >> 1, wn = wid & 1;
    const int gid = lane >> 2, tig = lane & 3;
    const int which = n0 >> 10;
    float* __restrict__ outp = (which == 0) ? g_q : (which == 1) ? g_k : g_v;
    const int nl0 = (n0 & 1023) + wn * 64;

#pragma unroll
    for (int mi = 0; mi < 2; ++mi) {
        const int r = m0 + wm * 32 + mi * 16 + gid;
        const int b = r >> 11, s = r & (S_ - 1);
#pragma unroll
        for (int j = 0; j < 8; ++j) {
            const int nl = nl0 + j * 8 + tig * 2;
            const int h = nl >> 6, d = nl & 63;
            const size_t base = ((size_t)(b * H_ + h) * S_ + s) * DH_ + d;
            *(float2*)(outp + base)            = make_float2(acc[mi][j][0], acc[mi][j][1]);
            *(float2*)(outp + base + 8 * DH_)  = make_float2(acc[mi][j][2], acc[mi][j][3]);
        }
    }
}

// =================================================================
// Output projection (HMMA) + residual: g_res = ctx @ W_O + x
// =================================================================
__global__ __launch_bounds__(256, 2) void proj_hmma(const float* __restrict__ x)
{
    __shared__ __align__(16) __nv_bfloat16 sAh[128 * SK];
    __shared__ __align__(16) __nv_bfloat16 sAl[128 * SK];
    __shared__ __align__(16) __nv_bfloat16 sBh[128 * SK];
    __shared__ __align__(16) __nv_bfloat16 sBl[128 * SK];

    const int m0 = blockIdx.x * 128;
    const int n0 = blockIdx.y * 128;          // 0..1023

    float acc[2][8][4] = {};
    hmma_core(g_cx_hi, g_cx_lo, g_wt_hi, g_wt_lo, m0, n0 + 3072,
              sAh, sAl, sBh, sBl, acc);

    const int tid = threadIdx.x, lane = tid & 31, wid = tid >> 5;
    const int wm = wid >> 1, wn = wid & 1;
    const int gid = lane >> 2, tig = lane & 3;
    const int nb = n0 + wn * 64;

#pragma unroll
    for (int mi = 0; mi < 2; ++mi) {
        const size_t r = m0 + wm * 32 + mi * 16 + gid;
#pragma unroll
        for (int j = 0; j < 8; ++j) {
            const size_t n = nb + j * 8 + tig * 2;
            float2 x0 = *(const float2*)(x + r * D_ + n);
            float2 x1 = *(const float2*)(x + (r + 8) * D_ + n);
            *(float2*)(g_res + r * D_ + n) =
                make_float2(acc[mi][j][0] + x0.x, acc[mi][j][1] + x0.y);
            *(float2*)(g_res + (r + 8) * D_ + n) =
                make_float2(acc[mi][j][2] + x1.x, acc[mi][j][3] + x1.y);
        }
    }
}

// =================================================================
// Flash attention (fp32 FFMA2, causal). One block = 64 queries/(b,h).
// Epilogue writes ctx as bf16 hi/lo split for the HMMA proj GEMM.
// =================================================================
__global__ __launch_bounds__(256, 2) void attn_kernel()
{
    extern __shared__ float smf[];
    float* Qt = smf;                // 64 x 68
    float* Kt = smf + 64 * 68;
    float* Vs = smf + 2 * 64 * 68;
    float* Pt = smf + 3 * 64 * 68;

    const int tid = threadIdx.x;
    const int tx = tid & 15, ty = tid >> 4;
    const int qt = blockIdx.x;
    const int bh = blockIdx.y;
    const int q0 = qt * 64;

    const float* __restrict__ Qg = g_q + (size_t)bh * S_ * DH_;
    const float* __restrict__ Kg = g_k + (size_t)bh * S_ * DH_;
    const float* __restrict__ Vg = g_v + (size_t)bh * S_ * DH_;

#pragma unroll
    for (int t = 0; t < 4; ++t) {
        int idx = tid + t * 256;
        int r = idx >> 4, c4 = (idx & 15) << 2;
        float4 v = *(const float4*)(Qg + (size_t)(q0 + r) * DH_ + c4);
        Qt[(c4 + 0) * 68 + r] = v.x * 0.125f;
        Qt[(c4 + 1) * 68 + r] = v.y * 0.125f;
        Qt[(c4 + 2) * 68 + r] = v.z * 0.125f;
        Qt[(c4 + 3) * 68 + r] = v.w * 0.125f;
    }

    u64 acc2[4][2] = {};
    float mrow[4] = {-1e30f, -1e30f, -1e30f, -1e30f};
    float lrow[4] = {};

    for (int kt = 0; kt <= qt; ++kt) {
        const int k0 = kt * 64;
#pragma unroll
        for (int t = 0; t < 4; ++t) {
            int idx = tid + t * 256;
            int r = idx >> 4, c4 = (idx & 15) << 2;
            float4 kv = *(const float4*)(Kg + (size_t)(k0 + r) * DH_ + c4);
            Kt[(c4 + 0) * 68 + r] = kv.x;
            Kt[(c4 + 1) * 68 + r] = kv.y;
            Kt[(c4 + 2) * 68 + r] = kv.z;
            Kt[(c4 + 3) * 68 + r] = kv.w;
            *(float4*)(Vs + r * 68 + c4) =
                *(const float4*)(Vg + (size_t)(k0 + r) * DH_ + c4);
        }
        __syncthreads();

        u64 sv2[4][2] = {};
#pragma unroll
        for (int d = 0; d < 64; ++d) {
            float4 qa = *(const float4*)(Qt + d * 68 + ty * 4);
            float4 kb = *(const float4*)(Kt + d * 68 + tx * 4);
            u64 b0 = pack2(kb.x, kb.y), b1 = pack2(kb.z, kb.w);
            float av[4] = { qa.x, qa.y, qa.z, qa.w };
#pragma unroll
            for (int i = 0; i < 4; i++) {
                u64 ad = dup2(av[i]);
                sv2[i][0] = ffma2(ad, b0, sv2[i][0]);
                sv2[i][1] = ffma2(ad, b1, sv2[i][1]);
            }
        }

        float sv[4][4];
#pragma unroll
        for (int i = 0; i < 4; i++) {
            unpack2(sv2[i][0], sv[i][0], sv[i][1]);
            unpack2(sv2[i][1], sv[i][2], sv[i][3]);
        }

        if (kt == qt) {
#pragma unroll
            for (int i = 0; i < 4; i++)
#pragma unroll
                for (int j = 0; j < 4; j++)
                    if (tx * 4 + j > ty * 4 + i) sv[i][j] = -1e30f;
        }

#pragma unroll
        for (int i = 0; i < 4; i++) {
            float tm = fmaxf(fmaxf(sv[i][0], sv[i][1]), fmaxf(sv[i][2], sv[i][3]));
            tm = fmaxf(tm, __shfl_xor_sync(0xffffffffu, tm, 1));
            tm = fmaxf(tm, __shfl_xor_sync(0xffffffffu, tm, 2));
            tm = fmaxf(tm, __shfl_xor_sync(0xffffffffu, tm, 4));
            tm = fmaxf(tm, __shfl_xor_sync(0xffffffffu, tm, 8));
            float mn = fmaxf(mrow[i], tm);
            float alpha = __expf(mrow[i] - mn);
            mrow[i] = mn;
            float psum = 0.f;
#pragma unroll
            for (int j = 0; j < 4; j++) {
                float p = __expf(sv[i][j] - mn);
                Pt[(tx * 4 + j) * 68 + ty * 4 + i] = p;
                psum += p;
            }
            psum += __shfl_xor_sync(0xffffffffu, psum, 1);
            psum += __shfl_xor_sync(0xffffffffu, psum, 2);
            psum += __shfl_xor_sync(0xffffffffu, psum, 4);
            psum += __shfl_xor_sync(0xffffffffu, psum, 8);
            lrow[i] = lrow[i] * alpha + psum;
            u64 al2 = dup2(alpha);
            acc2[i][0] = fmul2(acc2[i][0], al2);
            acc2[i][1] = fmul2(acc2[i][1], al2);
        }
        __syncthreads();

#pragma unroll
        for (int c = 0; c < 64; ++c) {
            float4 pa = *(const float4*)(Pt + c * 68 + ty * 4);
            float4 vb = *(const float4*)(Vs + c * 68 + tx * 4);
            u64 b0 = pack2(vb.x, vb.y), b1 = pack2(vb.z, vb.w);
            float av[4] = { pa.x, pa.y, pa.z, pa.w };
#pragma unroll
            for (int i = 0; i < 4; i++) {
                u64 ad = dup2(av[i]);
                acc2[i][0] = ffma2(ad, b0, acc2[i][0]);
                acc2[i][1] = ffma2(ad, b1, acc2[i][1]);
            }
        }
        __syncthreads();
    }

    const int b = bh >> 4, h = bh & 15;
#pragma unroll
    for (int i = 0; i < 4; i++) {
        float inv = 1.0f / lrow[i];
        size_t grow = (size_t)(b * S_ + q0 + ty * 4 + i) * D_ + h * 64;
#pragma unroll
        for (int jp = 0; jp < 2; jp++) {
            float2 f; unpack2(acc2[i][jp], f.x, f.y);
            f.x *= inv; f.y *= inv;
            __nv_bfloat16 h0 = __float2bfloat16(f.x);
            __nv_bfloat16 h1 = __float2bfloat16(f.y);
            __nv_bfloat162 hv; hv.x = h0; hv.y = h1;
            __nv_bfloat162 lv;
            lv.x = __float2bfloat16(f.x - __bfloat162float(h0));
            lv.y = __float2bfloat16(f.y - __bfloat162float(h1));
            size_t o = grow + tx * 4 + jp * 2;
            *(__nv_bfloat162*)(g_cx_hi + o) = hv;
            *(__nv_bfloat162*)(g_cx_lo + o) = lv;
        }
    }
}

// =================================================================
// LayerNorm over last dim (1024)
// =================================================================
__global__ __launch_bounds__(256) void ln_kernel(
    const float* __restrict__ gamma,
    const float* __restrict__ beta,
    float* __restrict__ out)
{
    __shared__ float ws[8], wq2[8];
    const int row = blockIdx.x;
    const int t = threadIdx.x;
    const int lane = t & 31, w = t >> 5;
    const float* rp = g_res + (size_t)row * D_;

    float4 v = *(const float4*)(rp + t * 4);
    float s = v.x + v.y + v.z + v.w;
    float q = v.x * v.x + v.y * v.y + v.z * v.z + v.w * v.w;
#pragma unroll
    for (int o = 16; o > 0; o >>= 1) {
        s += __shfl_xor_sync(0xffffffffu, s, o);
        q += __shfl_xor_sync(0xffffffffu, q, o);
    }
    if (lane == 0) { ws[w] = s; wq2[w] = q; }
    __syncthreads();
    float S = 0.f, Q = 0.f;
#pragma unroll
    for (int i = 0; i < 8; i++) { S += ws[i]; Q += wq2[i]; }

    float mu  = S * (1.0f / 1024.0f);
    float var = Q * (1.0f / 1024.0f) - mu * mu;
    float rstd = rsqrtf(var + 1e-5f);

    float4 g  = *(const float4*)(gamma + t * 4);
    float4 bt = *(const float4*)(beta  + t * 4);
    float4 o4;
    o4.x = (v.x - mu) * rstd * g.x + bt.x;
    o4.y = (v.y - mu) * rstd * g.y + bt.y;
    o4.z = (v.z - mu) * rstd * g.z + bt.z;
    o4.w = (v.w - mu) * rstd * g.w + bt.w;
    *(float4*)(out + (size_t)row * D_ + t * 4) = o4;
}

// =================================================================
extern "C" void kernel_launch(void* const* d_in, const int* in_sizes, int n_in,
                              void* d_out, int out_size)
{
    const float* x     = (const float*)d_in[0];
    const float* wq    = (const float*)d_in[1];
    const float* wk    = (const float*)d_in[2];
    const float* wv    = (const float*)d_in[3];
    const float* wo    = (const float*)d_in[4];
    const float* gamma = (const float*)d_in[5];
    const float* beta  = (const float*)d_in[6];
    float* out = (float*)d_out;

    cudaFuncSetAttribute(attn_kernel,
                         cudaFuncAttributeMaxDynamicSharedMemorySize, 69632);

    split_x<<<M_, 256>>>(x);
    wt_split<<<dim3(32, 128), dim3(32, 8)>>>(wq, wk, wv, wo);
    qkv_hmma<<<dim3(M_ / 128, 3072 / 128), 256>>>();
    attn_kernel<<<dim3(S_ / 64, B_ * H_), 256, 69632>>>();
    proj_hmma<<<dim3(M_ / 128, D_ / 128), 256>>>(x);
    ln_kernel<<<M_, 256>>>(gamma, beta, out);
}

// round 9
// speedup vs baseline: 2.3939x; 1.5655x over previous
#include <cuda_runtime.h>
#include <cuda_bf16.h>
#include <math.h>

#define B_  4
#define S_  2048
#define D_  1024
#define H_  16
#define DH_ 64
#define M_  (B_*S_)          // 8192 rows

typedef unsigned long long u64;
typedef unsigned int u32;

// ---------------- helpers ----------------------------------------
__device__ __forceinline__ u32 smem_u32(const void* p) {
    u32 a;
    asm("{ .reg .u64 t; cvta.to.shared.u64 t, %1; cvt.u32.u64 %0, t; }"
        : "=r"(a) : "l"(p));
    return a;
}
__device__ __forceinline__ void ldmx4(u32* r, u32 addr) {
    asm volatile("ldmatrix.sync.aligned.m8n8.x4.shared.b16 {%0,%1,%2,%3}, [%4];"
                 : "=r"(r[0]), "=r"(r[1]), "=r"(r[2]), "=r"(r[3]) : "r"(addr));
}
__device__ __forceinline__ void ldmx4t(u32* r, u32 addr) {
    asm volatile("ldmatrix.sync.aligned.m8n8.x4.trans.shared.b16 {%0,%1,%2,%3}, [%4];"
                 : "=r"(r[0]), "=r"(r[1]), "=r"(r[2]), "=r"(r[3]) : "r"(addr));
}
__device__ __forceinline__ void mma_bf16(float* c, const u32* a, u32 b0, u32 b1) {
    asm volatile(
        "mma.sync.aligned.m16n8k16.row.col.f32.bf16.bf16.f32 "
        "{%0,%1,%2,%3}, {%4,%5,%6,%7}, {%8,%9}, {%0,%1,%2,%3};"
        : "+f"(c[0]), "+f"(c[1]), "+f"(c[2]), "+f"(c[3])
        : "r"(a[0]), "r"(a[1]), "r"(a[2]), "r"(a[3]), "r"(b0), "r"(b1));
}
// pack two floats -> bf16x2 {lo, hi}
__device__ __forceinline__ u32 pkbf(float lo, float hi) {
    u32 r; asm("cvt.rn.bf16x2.f32 %0, %2, %1;" : "=r"(r) : "f"(lo), "f"(hi)); return r;
}
__device__ __forceinline__ float ex2f(float x) {
    float y; asm("ex2.approx.ftz.f32 %0, %1;" : "=f"(y) : "f"(x)); return y;
}
__device__ __forceinline__ float bf16rt(float v) {   // round-trip through bf16
    return __bfloat162float(__float2bfloat16(v));
}

// ---------------- scratch (no allocations allowed) ----------------
__device__ float g_res[(size_t)M_*D_];               // pre-layernorm
__device__ __nv_bfloat16 g_x_hi[(size_t)M_*D_];
__device__ __nv_bfloat16 g_x_lo[(size_t)M_*D_];
__device__ __nv_bfloat16 g_wt_hi[(size_t)4096*1024]; // [n][k]: 0-3071 WQKV^T, 3072-4095 WO^T
__device__ __nv_bfloat16 g_wt_lo[(size_t)4096*1024];
__device__ __nv_bfloat16 g_qh[(size_t)B_*H_*S_*DH_]; // [B,H,S,DH], q pre-scaled 0.125*log2e
__device__ __nv_bfloat16 g_ql[(size_t)B_*H_*S_*DH_];
__device__ __nv_bfloat16 g_kh[(size_t)B_*H_*S_*DH_];
__device__ __nv_bfloat16 g_kl[(size_t)B_*H_*S_*DH_];
__device__ __nv_bfloat16 g_vh[(size_t)B_*H_*S_*DH_];
__device__ __nv_bfloat16 g_vl[(size_t)B_*H_*S_*DH_];
__device__ __nv_bfloat16 g_cx_hi[(size_t)M_*D_];     // ctx split [m][k]
__device__ __nv_bfloat16 g_cx_lo[(size_t)M_*D_];

// =================================================================
// Prep: split x into bf16 hi/lo
// =================================================================
__global__ __launch_bounds__(256) void split_x(const float* __restrict__ x)
{
    size_t i = (size_t)blockIdx.x * 1024 + threadIdx.x * 4;
    float4 v = *(const float4*)(x + i);
    float h0 = bf16rt(v.x), h1 = bf16rt(v.y), h2 = bf16rt(v.z), h3 = bf16rt(v.w);
    *(u32*)(g_x_hi + i)     = pkbf(h0, h1);
    *(u32*)(g_x_hi + i + 2) = pkbf(h2, h3);
    *(u32*)(g_x_lo + i)     = pkbf(v.x - h0, v.y - h1);
    *(u32*)(g_x_lo + i + 2) = pkbf(v.z - h2, v.w - h3);
}

// =================================================================
// Prep: transpose W (k-major -> n-major) + split into bf16 hi/lo
// =================================================================
__global__ void wt_split(const float* __restrict__ wq, const float* __restrict__ wk,
                         const float* __restrict__ wv, const float* __restrict__ wo)
{
    __shared__ float tile[32][33];
    const int k0 = blockIdx.x * 32, n0 = blockIdx.y * 32;
    const int mat = n0 >> 10, c0 = n0 & 1023;
    const float* __restrict__ W = (mat == 0) ? wq : (mat == 1) ? wk : (mat == 2) ? wv : wo;
    const int tx = threadIdx.x, ty = threadIdx.y;
#pragma unroll
    for (int i = 0; i < 4; i++)
        tile[ty + i * 8][tx] = W[(size_t)(k0 + ty + i * 8) * 1024 + c0 + tx];
    __syncthreads();
#pragma unroll
    for (int i = 0; i < 4; i++) {
        int rr = ty + i * 8;
        float v = tile[tx][rr];
        float h = bf16rt(v);
        size_t o = (size_t)(n0 + rr) * 1024 + k0 + tx;
        g_wt_hi[o] = __float2bfloat16(h);
        g_wt_lo[o] = __float2bfloat16(v - h);
    }
}

// =================================================================
// HMMA GEMM core: C(128x128 f32) = Ah@Bh^T + Ah@Bl^T + Al@Bh^T
// =================================================================
#define SK 40   // padded smem row stride in bf16

__device__ __forceinline__ void ld_tile(const __nv_bfloat16* __restrict__ src,
                                        int row0, int k0,
                                        __nv_bfloat16* dst, int tid)
{
    const int row = tid >> 1, half = tid & 1;
    const uint4* s = (const uint4*)(src + (size_t)(row0 + row) * 1024 + k0 + half * 16);
    uint4* d = (uint4*)(dst + row * SK + half * 16);
    d[0] = s[0];
    d[1] = s[1];
}

__device__ __forceinline__ void hmma_core(
    const __nv_bfloat16* __restrict__ Ah, const __nv_bfloat16* __restrict__ Al,
    const __nv_bfloat16* __restrict__ Bh, const __nv_bfloat16* __restrict__ Bl,
    int m0, int n0row,
    __nv_bfloat16* sAh, __nv_bfloat16* sAl,
    __nv_bfloat16* sBh, __nv_bfloat16* sBl,
    float acc[2][8][4])
{
    const int tid = threadIdx.x;
    const int lane = tid & 31, wid = tid >> 5;
    const int wm = wid >> 1, wn = wid & 1;
    const int lrow = lane & 15, lcol = (lane >> 4) << 3;

    const u32 aHu = smem_u32(sAh), aLu = smem_u32(sAl);
    const u32 bHu = smem_u32(sBh), bLu = smem_u32(sBl);
    const u32 aoff = ((wm * 32 + lrow) * SK + lcol) * 2;
    const u32 boff = ((wn * 64 + lrow) * SK + lcol) * 2;

    for (int c = 0; c < 32; ++c) {
        const int k0 = c * 32;
        ld_tile(Ah, m0, k0, sAh, tid);
        ld_tile(Al, m0, k0, sAl, tid);
        ld_tile(Bh, n0row, k0, sBh, tid);
        ld_tile(Bl, n0row, k0, sBl, tid);
        __syncthreads();
#pragma unroll
        for (int ks = 0; ks < 2; ++ks) {
            const u32 kofs = ks * 32;
            u32 ah[2][4], al[2][4];
            ldmx4(ah[0], aHu + aoff + kofs);
            ldmx4(ah[1], aHu + aoff + 16 * SK * 2 + kofs);
            ldmx4(al[0], aLu + aoff + kofs);
            ldmx4(al[1], aLu + aoff + 16 * SK * 2 + kofs);
#pragma unroll
            for (int half = 0; half < 2; ++half) {
                const u32 hof = half * 32 * SK * 2;
                u32 bh[2][4], bl[2][4];
                ldmx4(bh[0], bHu + boff + hof + kofs);
                ldmx4(bh[1], bHu + boff + hof + 16 * SK * 2 + kofs);
                ldmx4(bl[0], bLu + boff + hof + kofs);
                ldmx4(bl[1], bLu + boff + hof + 16 * SK * 2 + kofs);
#pragma unroll
                for (int mi = 0; mi < 2; ++mi)
#pragma unroll
                    for (int jj = 0; jj < 4; ++jj) {
                        const int jb = jj >> 1, s = jj & 1;
                        float* cc = acc[mi][half * 4 + jj];
                        mma_bf16(cc, ah[mi], bh[jb][s], bh[jb][s + 2]);
                        mma_bf16(cc, ah[mi], bl[jb][s], bl[jb][s + 2]);
                        mma_bf16(cc, al[mi], bh[jb][s], bh[jb][s + 2]);
                    }
            }
        }
        __syncthreads();
    }
}

// =================================================================
// QKV GEMM (HMMA): write q/k/v as bf16 hi/lo [B,H,S,DH]; q scaled
// by 0.125*log2(e) so attention softmax runs in exp2 domain.
// =================================================================
__global__ __launch_bounds__(256, 2) void qkv_hmma()
{
    __shared__ __align__(16) __nv_bfloat16 sAh[128 * SK];
    __shared__ __align__(16) __nv_bfloat16 sAl[128 * SK];
    __shared__ __align__(16) __nv_bfloat16 sBh[128 * SK];
    __shared__ __align__(16) __nv_bfloat16 sBl[128 * SK];

    const int m0 = blockIdx.x * 128;
    const int n0 = blockIdx.y * 128;          // 0..3071

    float acc[2][8][4] = {};
    hmma_core(g_x_hi, g_x_lo, g_wt_hi, g_wt_lo, m0, n0, sAh, sAl, sBh, sBl, acc);

    const int tid = threadIdx.x, lane = tid & 31, wid = tid >> 5;
    const int wm = wid >> 1, wn = wid & 1;
    const int gid = lane >> 2, tig = lane & 3;
    const int which = n0 >> 10;
    __nv_bfloat16* __restrict__ oh = (which == 0) ? g_qh : (which == 1) ? g_kh : g_vh;
    __nv_bfloat16* __restrict__ ol = (which == 0) ? g_ql : (which == 1) ? g_kl : g_vl;
    const float sc = (which == 0) ? 0.125f * 1.4426950408889634f : 1.0f;
    const int nl0 = (n0 & 1023) + wn * 64;

#pragma unroll
    for (int mi = 0; mi < 2; ++mi) {
        const int r = m0 + wm * 32 + mi * 16 + gid;
        const int b = r >> 11, s = r & (S_ - 1);
#pragma unroll
        for (int j = 0; j < 8; ++j) {
            const int nl = nl0 + j * 8 + tig * 2;
            const int h = nl >> 6, d = nl & 63;
            const size_t base = ((size_t)(b * H_ + h) * S_ + s) * DH_ + d;
            float v0 = acc[mi][j][0] * sc, v1 = acc[mi][j][1] * sc;
            float v2 = acc[mi][j][2] * sc, v3 = acc[mi][j][3] * sc;
            float h0 = bf16rt(v0), h1 = bf16rt(v1), h2 = bf16rt(v2), h3 = bf16rt(v3);
            *(u32*)(oh + base)           = pkbf(h0, h1);
            *(u32*)(ol + base)           = pkbf(v0 - h0, v1 - h1);
            *(u32*)(oh + base + 8 * DH_) = pkbf(h2, h3);
            *(u32*)(ol + base + 8 * DH_) = pkbf(v2 - h2, v3 - h3);
        }
    }
}

// =================================================================
// Output projection (HMMA) + residual: g_res = ctx @ W_O + x
// =================================================================
__global__ __launch_bounds__(256, 2) void proj_hmma(const float* __restrict__ x)
{
    __shared__ __align__(16) __nv_bfloat16 sAh[128 * SK];
    __shared__ __align__(16) __nv_bfloat16 sAl[128 * SK];
    __shared__ __align__(16) __nv_bfloat16 sBh[128 * SK];
    __shared__ __align__(16) __nv_bfloat16 sBl[128 * SK];

    const int m0 = blockIdx.x * 128;
    const int n0 = blockIdx.y * 128;          // 0..1023

    float acc[2][8][4] = {};
    hmma_core(g_cx_hi, g_cx_lo, g_wt_hi, g_wt_lo, m0, n0 + 3072,
              sAh, sAl, sBh, sBl, acc);

    const int tid = threadIdx.x, lane = tid & 31, wid = tid >> 5;
    const int wm = wid >> 1, wn = wid & 1;
    const int gid = lane >> 2, tig = lane & 3;
    const int nb = n0 + wn * 64;

#pragma unroll
    for (int mi = 0; mi < 2; ++mi) {
        const size_t r = m0 + wm * 32 + mi * 16 + gid;
#pragma unroll
        for (int j = 0; j < 8; ++j) {
            const size_t n = nb + j * 8 + tig * 2;
            float2 x0 = *(const float2*)(x + r * D_ + n);
            float2 x1 = *(const float2*)(x + (r + 8) * D_ + n);
            *(float2*)(g_res + r * D_ + n) =
                make_float2(acc[mi][j][0] + x0.x, acc[mi][j][1] + x0.y);
            *(float2*)(g_res + (r + 8) * D_ + n) =
                make_float2(acc[mi][j][2] + x1.x, acc[mi][j][3] + x1.y);
        }
    }
}

// =================================================================
// Flash attention (HMMA bf16 split, causal, exp2 domain).
// Block = 128 queries of one (b,h); 8 warps x 16 rows; K-tile 64.
// =================================================================
#define SKA 72

__global__ __launch_bounds__(256) void attn_hmma()
{
    __shared__ __align__(16) __nv_bfloat16 smA[128 * SKA];  // Kh|Kl ; Q-stage hi
    __shared__ __align__(16) __nv_bfloat16 smB[128 * SKA];  // Vh|Vl ; Q-stage lo

    const int tid = threadIdx.x, lane = tid & 31, wm = tid >> 5;
    const int qt = blockIdx.x, bh = blockIdx.y;
    const int q0 = qt * 128;
    const size_t gb = (size_t)bh * S_ * DH_;

    // ---- stage Q hi/lo, load per-warp A fragments
    {
        const int row = tid >> 1, c = (tid & 1) * 32;
        const uint4* sh = (const uint4*)(g_qh + gb + (size_t)(q0 + row) * DH_ + c);
        const uint4* sl = (const uint4*)(g_ql + gb + (size_t)(q0 + row) * DH_ + c);
        uint4* dh = (uint4*)(smA + row * SKA + c);
        uint4* dl = (uint4*)(smB + row * SKA + c);
#pragma unroll
        for (int i = 0; i < 4; i++) { dh[i] = sh[i]; dl[i] = sl[i]; }
    }
    __syncthreads();
    u32 qh[4][4], ql[4][4];
    {
        const u32 ah = smem_u32(smA), al = smem_u32(smB);
        const u32 off = ((wm * 16 + (lane & 15)) * SKA + (lane >> 4) * 8) * 2;
#pragma unroll
        for (int ks = 0; ks < 4; ks++) {
            ldmx4(qh[ks], ah + off + ks * 32);
            ldmx4(ql[ks], al + off + ks * 32);
        }
    }
    __syncthreads();

    float o[8][4] = {};
    float mA = -1e30f, mB = -1e30f, lA = 0.f, lB = 0.f;
    const int rowA = q0 + wm * 16 + (lane >> 2);
    const u32 kh_b = smem_u32(smA), kl_b = kh_b + 64 * SKA * 2;
    const u32 vh_b = smem_u32(smB), vl_b = vh_b + 64 * SKA * 2;
    const u32 sboff = ((lane & 15) * SKA + (lane >> 4) * 8) * 2;
    const u32 vtoff = ((((lane >> 3) & 1) * 8 + (lane & 7)) * SKA + (lane >> 4) * 8) * 2;

    for (int kt = 0; kt <= 2 * qt + 1; ++kt) {
        const int k0t = kt * 64;
        {   // load K/V tiles hi/lo (64x64 each)
            const int row = tid >> 2, c = (tid & 3) * 16;
            const size_t g = gb + (size_t)(k0t + row) * DH_ + c;
            const uint4* s0 = (const uint4*)(g_kh + g);
            const uint4* s1 = (const uint4*)(g_kl + g);
            const uint4* s2 = (const uint4*)(g_vh + g);
            const uint4* s3 = (const uint4*)(g_vl + g);
            uint4* d0 = (uint4*)(smA + row * SKA + c);
            uint4* d1 = (uint4*)(smA + 64 * SKA + row * SKA + c);
            uint4* d2 = (uint4*)(smB + row * SKA + c);
            uint4* d3 = (uint4*)(smB + 64 * SKA + row * SKA + c);
            d0[0] = s0[0]; d0[1] = s0[1];
            d1[0] = s1[0]; d1[1] = s1[1];
            d2[0] = s2[0]; d2[1] = s2[1];
            d3[0] = s3[0]; d3[1] = s3[1];
        }
        __syncthreads();

        if (k0t <= q0 + wm * 16 + 15) {   // warp-uniform: skip fully-masked tiles
            // ---- S = Q K^T (3-term split), f32 accum
            float s[8][4] = {};
#pragma unroll
            for (int ks = 0; ks < 4; ks++)
#pragma unroll
                for (int g = 0; g < 4; g++) {
                    u32 kh4[4], kl4[4];
                    ldmx4(kh4, kh_b + sboff + g * 16 * SKA * 2 + ks * 32);
                    ldmx4(kl4, kl_b + sboff + g * 16 * SKA * 2 + ks * 32);
                    mma_bf16(s[2 * g],     qh[ks], kh4[0], kh4[2]);
                    mma_bf16(s[2 * g],     qh[ks], kl4[0], kl4[2]);
                    mma_bf16(s[2 * g],     ql[ks], kh4[0], kh4[2]);
                    mma_bf16(s[2 * g + 1], qh[ks], kh4[1], kh4[3]);
                    mma_bf16(s[2 * g + 1], qh[ks], kl4[1], kl4[3]);
                    mma_bf16(s[2 * g + 1], ql[ks], kh4[1], kh4[3]);
                }

            // ---- causal mask (diagonal tiles only)
            if (k0t + 63 > q0 + wm * 16) {
#pragma unroll
                for (int b = 0; b < 8; b++) {
                    int cb = k0t + b * 8 + (lane & 3) * 2;
                    if (cb > rowA)         s[b][0] = -1e30f;
                    if (cb + 1 > rowA)     s[b][1] = -1e30f;
                    if (cb > rowA + 8)     s[b][2] = -1e30f;
                    if (cb + 1 > rowA + 8) s[b][3] = -1e30f;
                }
            }

            // ---- online softmax (exp2 domain; quad lanes share a row)
            float nmA = mA, nmB = mB;
#pragma unroll
            for (int b = 0; b < 8; b++) {
                nmA = fmaxf(nmA, fmaxf(s[b][0], s[b][1]));
                nmB = fmaxf(nmB, fmaxf(s[b][2], s[b][3]));
            }
            nmA = fmaxf(nmA, __shfl_xor_sync(~0u, nmA, 1));
            nmA = fmaxf(nmA, __shfl_xor_sync(~0u, nmA, 2));
            nmB = fmaxf(nmB, __shfl_xor_sync(~0u, nmB, 1));
            nmB = fmaxf(nmB, __shfl_xor_sync(~0u, nmB, 2));
            float alA = ex2f(mA - nmA), alB = ex2f(mB - nmB);
            mA = nmA; mB = nmB;
#pragma unroll
            for (int b = 0; b < 8; b++) {
                o[b][0] *= alA; o[b][1] *= alA;
                o[b][2] *= alB; o[b][3] *= alB;
            }

            // ---- P = exp2(S-m), split hi/lo, PV (3-term) per kstep
            float sumA = 0.f, sumB = 0.f;
#pragma unroll
            for (int ks = 0; ks < 4; ks++) {
                float p[8];
                p[0] = ex2f(s[2 * ks][0] - mA);     p[1] = ex2f(s[2 * ks][1] - mA);
                p[2] = ex2f(s[2 * ks][2] - mB);     p[3] = ex2f(s[2 * ks][3] - mB);
                p[4] = ex2f(s[2 * ks + 1][0] - mA); p[5] = ex2f(s[2 * ks + 1][1] - mA);
                p[6] = ex2f(s[2 * ks + 1][2] - mB); p[7] = ex2f(s[2 * ks + 1][3] - mB);
                sumA += p[0] + p[1] + p[4] + p[5];
                sumB += p[2] + p[3] + p[6] + p[7];
                float hf[8];
#pragma unroll
                for (int e = 0; e < 8; e++) hf[e] = bf16rt(p[e]);
                u32 ph4[4], pl4[4];
                ph4[0] = pkbf(hf[0], hf[1]); ph4[1] = pkbf(hf[2], hf[3]);
                ph4[2] = pkbf(hf[4], hf[5]); ph4[3] = pkbf(hf[6], hf[7]);
                pl4[0] = pkbf(p[0] - hf[0], p[1] - hf[1]);
                pl4[1] = pkbf(p[2] - hf[2], p[3] - hf[3]);
                pl4[2] = pkbf(p[4] - hf[4], p[5] - hf[5]);
                pl4[3] = pkbf(p[6] - hf[6], p[7] - hf[7]);
#pragma unroll
                for (int g = 0; g < 4; g++) {
                    u32 vh4[4], vl4[4];
                    ldmx4t(vh4, vh_b + vtoff + ks * 16 * SKA * 2 + g * 32);
                    ldmx4t(vl4, vl_b + vtoff + ks * 16 * SKA * 2 + g * 32);
                    mma_bf16(o[2 * g],     ph4, vh4[0], vh4[1]);
                    mma_bf16(o[2 * g],     ph4, vl4[0], vl4[1]);
                    mma_bf16(o[2 * g],     pl4, vh4[0], vh4[1]);
                    mma_bf16(o[2 * g + 1], ph4, vh4[2], vh4[3]);
                    mma_bf16(o[2 * g + 1], ph4, vl4[2], vl4[3]);
                    mma_bf16(o[2 * g + 1], pl4, vh4[2], vh4[3]);
                }
            }
            sumA += __shfl_xor_sync(~0u, sumA, 1);
            sumA += __shfl_xor_sync(~0u, sumA, 2);
            sumB += __shfl_xor_sync(~0u, sumB, 1);
            sumB += __shfl_xor_sync(~0u, sumB, 2);
            lA = lA * alA + sumA;
            lB = lB * alB + sumB;
        }
        __syncthreads();
    }

    // ---- write ctx as bf16 hi/lo [m][1024] for proj GEMM
    const float iA = 1.0f / lA, iB = 1.0f / lB;
    const int bb = bh >> 4, hh = bh & 15;
    const size_t m0r = (size_t)(bb * S_ + rowA) * D_ + hh * 64;
    const size_t m1r = m0r + 8 * D_;
#pragma unroll
    for (int b = 0; b < 8; b++) {
        int col = b * 8 + (lane & 3) * 2;
        float f0 = o[b][0] * iA, f1 = o[b][1] * iA;
        float f2 = o[b][2] * iB, f3 = o[b][3] * iB;
        float h0 = bf16rt(f0), h1 = bf16rt(f1), h2 = bf16rt(f2), h3 = bf16rt(f3);
        *(u32*)(g_cx_hi + m0r + col) = pkbf(h0, h1);
        *(u32*)(g_cx_lo + m0r + col) = pkbf(f0 - h0, f1 - h1);
        *(u32*)(g_cx_hi + m1r + col) = pkbf(h2, h3);
        *(u32*)(g_cx_lo + m1r + col) = pkbf(f2 - h2, f3 - h3);
    }
}

// =================================================================
// LayerNorm over last dim (1024)
// =================================================================
__global__ __launch_bounds__(256) void ln_kernel(
    const float* __restrict__ gamma,
    const float* __restrict__ beta,
    float* __restrict__ out)
{
    __shared__ float ws[8], wq2[8];
    const int row = blockIdx.x;
    const int t = threadIdx.x;
    const int lane = t & 31, w = t >> 5;
    const float* rp = g_res + (size_t)row * D_;

    float4 v = *(const float4*)(rp + t * 4);
    float s = v.x + v.y + v.z + v.w;
    float q = v.x * v.x + v.y * v.y + v.z * v.z + v.w * v.w;
#pragma unroll
    for (int o = 16; o > 0; o >>= 1) {
        s += __shfl_xor_sync(0xffffffffu, s, o);
        q += __shfl_xor_sync(0xffffffffu, q, o);
    }
    if (lane == 0) { ws[w] = s; wq2[w] = q; }
    __syncthreads();
    float S = 0.f, Q = 0.f;
#pragma unroll
    for (int i = 0; i < 8; i++) { S += ws[i]; Q += wq2[i]; }

    float mu  = S * (1.0f / 1024.0f);
    float var = Q * (1.0f / 1024.0f) - mu * mu;
    float rstd = rsqrtf(var + 1e-5f);

    float4 g  = *(const float4*)(gamma + t * 4);
    float4 bt = *(const float4*)(beta  + t * 4);
    float4 o4;
    o4.x = (v.x - mu) * rstd * g.x + bt.x;
    o4.y = (v.y - mu) * rstd * g.y + bt.y;
    o4.z = (v.z - mu) * rstd * g.z + bt.z;
    o4.w = (v.w - mu) * rstd * g.w + bt.w;
    *(float4*)(out + (size_t)row * D_ + t * 4) = o4;
}

// =================================================================
extern "C" void kernel_launch(void* const* d_in, const int* in_sizes, int n_in,
                              void* d_out, int out_size)
{
    const float* x     = (const float*)d_in[0];
    const float* wq    = (const float*)d_in[1];
    const float* wk    = (const float*)d_in[2];
    const float* wv    = (const float*)d_in[3];
    const float* wv2   = (const float*)d_in[4];
    const float* gamma = (const float*)d_in[5];
    const float* beta  = (const float*)d_in[6];
    float* out = (float*)d_out;

    split_x<<<M_, 256>>>(x);
    wt_split<<<dim3(32, 128), dim3(32, 8)>>>(wq, wk, wv, wv2);
    qkv_hmma<<<dim3(M_ / 128, 3072 / 128), 256>>>();
    attn_hmma<<<dim3(S_ / 128, B_ * H_), 256>>>();
    proj_hmma<<<dim3(M_ / 128, D_ / 128), 256>>>(x);
    ln_kernel<<<M_, 256>>>(gamma, beta, out);
}

// round 10
// speedup vs baseline: 2.4918x; 1.0409x over previous
#include <cuda_runtime.h>
#include <cuda_bf16.h>
#include <math.h>

#define B_  4
#define S_  2048
#define D_  1024
#define H_  16
#define DH_ 64
#define M_  (B_*S_)          // 8192 rows

typedef unsigned long long u64;
typedef unsigned int u32;

// ---------------- helpers ----------------------------------------
__device__ __forceinline__ u32 smem_u32(const void* p) {
    u32 a;
    asm("{ .reg .u64 t; cvta.to.shared.u64 t, %1; cvt.u32.u64 %0, t; }"
        : "=r"(a) : "l"(p));
    return a;
}
__device__ __forceinline__ void ldmx4(u32* r, u32 addr) {
    asm volatile("ldmatrix.sync.aligned.m8n8.x4.shared.b16 {%0,%1,%2,%3}, [%4];"
                 : "=r"(r[0]), "=r"(r[1]), "=r"(r[2]), "=r"(r[3]) : "r"(addr));
}
__device__ __forceinline__ void ldmx4t(u32* r, u32 addr) {
    asm volatile("ldmatrix.sync.aligned.m8n8.x4.trans.shared.b16 {%0,%1,%2,%3}, [%4];"
                 : "=r"(r[0]), "=r"(r[1]), "=r"(r[2]), "=r"(r[3]) : "r"(addr));
}
__device__ __forceinline__ void mma_bf16(float* c, const u32* a, u32 b0, u32 b1) {
    asm volatile(
        "mma.sync.aligned.m16n8k16.row.col.f32.bf16.bf16.f32 "
        "{%0,%1,%2,%3}, {%4,%5,%6,%7}, {%8,%9}, {%0,%1,%2,%3};"
        : "+f"(c[0]), "+f"(c[1]), "+f"(c[2]), "+f"(c[3])
        : "r"(a[0]), "r"(a[1]), "r"(a[2]), "r"(a[3]), "r"(b0), "r"(b1));
}
__device__ __forceinline__ u32 pkbf(float lo, float hi) {
    u32 r; asm("cvt.rn.bf16x2.f32 %0, %2, %1;" : "=r"(r) : "f"(lo), "f"(hi)); return r;
}
__device__ __forceinline__ float ex2f(float x) {
    float y; asm("ex2.approx.ftz.f32 %0, %1;" : "=f"(y) : "f"(x)); return y;
}
__device__ __forceinline__ float bf16rt(float v) {
    return __bfloat162float(__float2bfloat16(v));
}
__device__ __forceinline__ void cpa16(u32 dst, const void* src) {
    asm volatile("cp.async.cg.shared.global [%0], [%1], 16;"
                 :: "r"(dst), "l"(__cvta_generic_to_global(src)) : "memory");
}
__device__ __forceinline__ void cp_commit() {
    asm volatile("cp.async.commit_group;" ::: "memory");
}
__device__ __forceinline__ void cp_wait0() {
    asm volatile("cp.async.wait_group 0;" ::: "memory");
}

// ---------------- scratch (no allocations allowed) ----------------
__device__ float g_res[(size_t)M_*D_];               // pre-layernorm
__device__ __nv_bfloat16 g_x_hi[(size_t)M_*D_];
__device__ __nv_bfloat16 g_x_lo[(size_t)M_*D_];
__device__ __nv_bfloat16 g_wt_hi[(size_t)4096*1024]; // [n][k]: 0-3071 WQKV^T, 3072-4095 WO^T
__device__ __nv_bfloat16 g_wt_lo[(size_t)4096*1024];
__device__ __nv_bfloat16 g_qh[(size_t)B_*H_*S_*DH_]; // [B,H,S,DH], q pre-scaled 0.125*log2e
__device__ __nv_bfloat16 g_ql[(size_t)B_*H_*S_*DH_];
__device__ __nv_bfloat16 g_kh[(size_t)B_*H_*S_*DH_];
__device__ __nv_bfloat16 g_kl[(size_t)B_*H_*S_*DH_];
__device__ __nv_bfloat16 g_vh[(size_t)B_*H_*S_*DH_];
__device__ __nv_bfloat16 g_vl[(size_t)B_*H_*S_*DH_];
__device__ __nv_bfloat16 g_cx_hi[(size_t)M_*D_];     // ctx split [m][k]
__device__ __nv_bfloat16 g_cx_lo[(size_t)M_*D_];

// =================================================================
// Prep: split x into bf16 hi/lo
// =================================================================
__global__ __launch_bounds__(256) void split_x(const float* __restrict__ x)
{
    size_t i = (size_t)blockIdx.x * 1024 + threadIdx.x * 4;
    float4 v = *(const float4*)(x + i);
    float h0 = bf16rt(v.x), h1 = bf16rt(v.y), h2 = bf16rt(v.z), h3 = bf16rt(v.w);
    *(u32*)(g_x_hi + i)     = pkbf(h0, h1);
    *(u32*)(g_x_hi + i + 2) = pkbf(h2, h3);
    *(u32*)(g_x_lo + i)     = pkbf(v.x - h0, v.y - h1);
    *(u32*)(g_x_lo + i + 2) = pkbf(v.z - h2, v.w - h3);
}

// =================================================================
// Prep: transpose W (k-major -> n-major) + split into bf16 hi/lo
// =================================================================
__global__ void wt_split(const float* __restrict__ wq, const float* __restrict__ wk,
                         const float* __restrict__ wv, const float* __restrict__ wo)
{
    __shared__ float tile[32][33];
    const int k0 = blockIdx.x * 32, n0 = blockIdx.y * 32;
    const int mat = n0 >> 10, c0 = n0 & 1023;
    const float* __restrict__ W = (mat == 0) ? wq : (mat == 1) ? wk : (mat == 2) ? wv : wo;
    const int tx = threadIdx.x, ty = threadIdx.y;
#pragma unroll
    for (int i = 0; i < 4; i++)
        tile[ty + i * 8][tx] = W[(size_t)(k0 + ty + i * 8) * 1024 + c0 + tx];
    __syncthreads();
#pragma unroll
    for (int i = 0; i < 4; i++) {
        int rr = ty + i * 8;
        float v = tile[tx][rr];
        float h = bf16rt(v);
        size_t o = (size_t)(n0 + rr) * 1024 + k0 + tx;
        g_wt_hi[o] = __float2bfloat16(h);
        g_wt_lo[o] = __float2bfloat16(v - h);
    }
}

// =================================================================
// HMMA GEMM core (cp.async double-buffered):
// C(128x128 f32) = Ah@Bh^T + Ah@Bl^T + Al@Bh^T
// =================================================================
#define SK 40                       // smem row stride in bf16 (80B)
#define TILE_BYTES  (128 * SK * 2)  // 10240
#define STAGE_BYTES (4 * TILE_BYTES)

__device__ __forceinline__ void gemm_prefetch(
    const __nv_bfloat16* __restrict__ Ah, const __nv_bfloat16* __restrict__ Al,
    const __nv_bfloat16* __restrict__ Bh, const __nv_bfloat16* __restrict__ Bl,
    int m0, int n0row, int k0, u32 st, int row, int half)
{
    const u32 cpo = (u32)(row * SK + half * 16) * 2;
    const size_t ga = (size_t)(m0 + row) * 1024 + k0 + half * 16;
    const size_t gn = (size_t)(n0row + row) * 1024 + k0 + half * 16;
    cpa16(st + cpo,                       Ah + ga);
    cpa16(st + cpo + 16,                  Ah + ga + 8);
    cpa16(st + TILE_BYTES + cpo,          Al + ga);
    cpa16(st + TILE_BYTES + cpo + 16,     Al + ga + 8);
    cpa16(st + 2 * TILE_BYTES + cpo,      Bh + gn);
    cpa16(st + 2 * TILE_BYTES + cpo + 16, Bh + gn + 8);
    cpa16(st + 3 * TILE_BYTES + cpo,      Bl + gn);
    cpa16(st + 3 * TILE_BYTES + cpo + 16, Bl + gn + 8);
    cp_commit();
}

__device__ __forceinline__ void hmma_core(
    const __nv_bfloat16* __restrict__ Ah, const __nv_bfloat16* __restrict__ Al,
    const __nv_bfloat16* __restrict__ Bh, const __nv_bfloat16* __restrict__ Bl,
    int m0, int n0row, __nv_bfloat16* sm, float acc[2][8][4])
{
    const int tid = threadIdx.x;
    const int lane = tid & 31, wid = tid >> 5;
    const int wm = wid >> 1, wn = wid & 1;
    const int lrow = lane & 15, lcol = (lane >> 4) << 3;
    const int row = tid >> 1, half = tid & 1;

    const u32 sb = smem_u32(sm);
    const u32 aoff = (u32)((wm * 32 + lrow) * SK + lcol) * 2;
    const u32 boff = (u32)((wn * 64 + lrow) * SK + lcol) * 2;

    gemm_prefetch(Ah, Al, Bh, Bl, m0, n0row, 0, sb, row, half);

    for (int c = 0; c < 32; ++c) {
        cp_wait0();
        __syncthreads();
        if (c + 1 < 32)
            gemm_prefetch(Ah, Al, Bh, Bl, m0, n0row, (c + 1) * 32,
                          sb + ((c + 1) & 1) * STAGE_BYTES, row, half);

        const u32 st = sb + (c & 1) * STAGE_BYTES;
        const u32 aH = st + aoff, aL = st + TILE_BYTES + aoff;
        const u32 bH = st + 2 * TILE_BYTES + boff, bL = st + 3 * TILE_BYTES + boff;
#pragma unroll
        for (int ks = 0; ks < 2; ++ks) {
            const u32 kofs = ks * 32;
            u32 ah[2][4], al[2][4];
            ldmx4(ah[0], aH + kofs);
            ldmx4(ah[1], aH + 16 * SK * 2 + kofs);
            ldmx4(al[0], aL + kofs);
            ldmx4(al[1], aL + 16 * SK * 2 + kofs);
#pragma unroll
            for (int hf = 0; hf < 2; ++hf) {
                const u32 ho = hf * 32 * SK * 2;
                u32 bh[2][4], bl[2][4];
                ldmx4(bh[0], bH + ho + kofs);
                ldmx4(bh[1], bH + ho + 16 * SK * 2 + kofs);
                ldmx4(bl[0], bL + ho + kofs);
                ldmx4(bl[1], bL + ho + 16 * SK * 2 + kofs);
#pragma unroll
                for (int mi = 0; mi < 2; ++mi)
#pragma unroll
                    for (int jj = 0; jj < 4; ++jj) {
                        const int jb = jj >> 1, s = jj & 1;
                        float* cc = acc[mi][hf * 4 + jj];
                        mma_bf16(cc, ah[mi], bh[jb][s], bh[jb][s + 2]);
                        mma_bf16(cc, ah[mi], bl[jb][s], bl[jb][s + 2]);
                        mma_bf16(cc, al[mi], bh[jb][s], bh[jb][s + 2]);
                    }
            }
        }
    }
}

// =================================================================
// QKV GEMM (HMMA): write q/k/v as bf16 hi/lo [B,H,S,DH]; q scaled
// by 0.125*log2(e) so attention softmax runs in exp2 domain.
// =================================================================
__global__ __launch_bounds__(256, 2) void qkv_hmma()
{
    extern __shared__ __nv_bfloat16 dynsm[];
    const int m0 = blockIdx.x * 128;
    const int n0 = blockIdx.y * 128;          // 0..3071

    float acc[2][8][4] = {};
    hmma_core(g_x_hi, g_x_lo, g_wt_hi, g_wt_lo, m0, n0, dynsm, acc);

    const int tid = threadIdx.x, lane = tid & 31, wid = tid >> 5;
    const int wm = wid >> 1, wn = wid & 1;
    const int gid = lane >> 2, tig = lane & 3;
    const int which = n0 >> 10;
    __nv_bfloat16* __restrict__ oh = (which == 0) ? g_qh : (which == 1) ? g_kh : g_vh;
    __nv_bfloat16* __restrict__ ol = (which == 0) ? g_ql : (which == 1) ? g_kl : g_vl;
    const float sc = (which == 0) ? 0.125f * 1.4426950408889634f : 1.0f;
    const int nl0 = (n0 & 1023) + wn * 64;

#pragma unroll
    for (int mi = 0; mi < 2; ++mi) {
        const int r = m0 + wm * 32 + mi * 16 + gid;
        const int b = r >> 11, s = r & (S_ - 1);
#pragma unroll
        for (int j = 0; j < 8; ++j) {
            const int nl = nl0 + j * 8 + tig * 2;
            const int h = nl >> 6, d = nl & 63;
            const size_t base = ((size_t)(b * H_ + h) * S_ + s) * DH_ + d;
            float v0 = acc[mi][j][0] * sc, v1 = acc[mi][j][1] * sc;
            float v2 = acc[mi][j][2] * sc, v3 = acc[mi][j][3] * sc;
            float h0 = bf16rt(v0), h1 = bf16rt(v1), h2 = bf16rt(v2), h3 = bf16rt(v3);
            *(u32*)(oh + base)           = pkbf(h0, h1);
            *(u32*)(ol + base)           = pkbf(v0 - h0, v1 - h1);
            *(u32*)(oh + base + 8 * DH_) = pkbf(h2, h3);
            *(u32*)(ol + base + 8 * DH_) = pkbf(v2 - h2, v3 - h3);
        }
    }
}

// =================================================================
// Output projection (HMMA) + residual: g_res = ctx @ W_O + x
// =================================================================
__global__ __launch_bounds__(256, 2) void proj_hmma(const float* __restrict__ x)
{
    extern __shared__ __nv_bfloat16 dynsm[];
    const int m0 = blockIdx.x * 128;
    const int n0 = blockIdx.y * 128;          // 0..1023

    float acc[2][8][4] = {};
    hmma_core(g_cx_hi, g_cx_lo, g_wt_hi, g_wt_lo, m0, n0 + 3072, dynsm, acc);

    const int tid = threadIdx.x, lane = tid & 31, wid = tid >> 5;
    const int wm = wid >> 1, wn = wid & 1;
    const int gid = lane >> 2, tig = lane & 3;
    const int nb = n0 + wn * 64;

#pragma unroll
    for (int mi = 0; mi < 2; ++mi) {
        const size_t r = m0 + wm * 32 + mi * 16 + gid;
#pragma unroll
        for (int j = 0; j < 8; ++j) {
            const size_t n = nb + j * 8 + tig * 2;
            float2 x0 = *(const float2*)(x + r * D_ + n);
            float2 x1 = *(const float2*)(x + (r + 8) * D_ + n);
            *(float2*)(g_res + r * D_ + n) =
                make_float2(acc[mi][j][0] + x0.x, acc[mi][j][1] + x0.y);
            *(float2*)(g_res + (r + 8) * D_ + n) =
                make_float2(acc[mi][j][2] + x1.x, acc[mi][j][3] + x1.y);
        }
    }
}

// =================================================================
// Flash attention (HMMA bf16 split, causal, exp2 domain).
// Block = 64 queries of one (b,h); 4 warps x 16 rows; K-tile 64.
// 128 threads, 3 CTAs/SM for latency hiding.
// =================================================================
#define SKA 72

__global__ __launch_bounds__(128, 3) void attn_hmma()
{
    __shared__ __align__(16) __nv_bfloat16 smA[128 * SKA];  // Kh|Kl ; Q-stage hi
    __shared__ __align__(16) __nv_bfloat16 smB[128 * SKA];  // Vh|Vl ; Q-stage lo

    const int tid = threadIdx.x, lane = tid & 31, wm = tid >> 5;
    const int qt = blockIdx.x, bh = blockIdx.y;
    const int q0 = qt * 64;
    const size_t gb = (size_t)bh * S_ * DH_;

    // ---- stage Q hi/lo (64 rows), load per-warp A fragments
    {
        const int row = tid >> 1, c = (tid & 1) * 32;
        const uint4* sh = (const uint4*)(g_qh + gb + (size_t)(q0 + row) * DH_ + c);
        const uint4* sl = (const uint4*)(g_ql + gb + (size_t)(q0 + row) * DH_ + c);
        uint4* dh = (uint4*)(smA + row * SKA + c);
        uint4* dl = (uint4*)(smB + row * SKA + c);
#pragma unroll
        for (int i = 0; i < 4; i++) { dh[i] = sh[i]; dl[i] = sl[i]; }
    }
    __syncthreads();
    u32 qh[4][4], ql[4][4];
    {
        const u32 ah = smem_u32(smA), al = smem_u32(smB);
        const u32 off = ((wm * 16 + (lane & 15)) * SKA + (lane >> 4) * 8) * 2;
#pragma unroll
        for (int ks = 0; ks < 4; ks++) {
            ldmx4(qh[ks], ah + off + ks * 32);
            ldmx4(ql[ks], al + off + ks * 32);
        }
    }
    __syncthreads();

    float o[8][4] = {};
    float mA = -1e30f, mB = -1e30f, lA = 0.f, lB = 0.f;
    const int rowA = q0 + wm * 16 + (lane >> 2);
    const u32 kh_b = smem_u32(smA), kl_b = kh_b + 64 * SKA * 2;
    const u32 vh_b = smem_u32(smB), vl_b = vh_b + 64 * SKA * 2;
    const u32 sboff = ((lane & 15) * SKA + (lane >> 4) * 8) * 2;
    const u32 vtoff = ((((lane >> 3) & 1) * 8 + (lane & 7)) * SKA + (lane >> 4) * 8) * 2;

    for (int kt = 0; kt <= qt; ++kt) {
        const int k0t = kt * 64;
        {   // load K/V tiles hi/lo (64x64 each), 128 threads
            const int row = tid >> 1, c = (tid & 1) * 32;
            const size_t g = gb + (size_t)(k0t + row) * DH_ + c;
            const uint4* s0 = (const uint4*)(g_kh + g);
            const uint4* s1 = (const uint4*)(g_kl + g);
            const uint4* s2 = (const uint4*)(g_vh + g);
            const uint4* s3 = (const uint4*)(g_vl + g);
            uint4* d0 = (uint4*)(smA + row * SKA + c);
            uint4* d1 = (uint4*)(smA + (64 + row) * SKA + c);
            uint4* d2 = (uint4*)(smB + row * SKA + c);
            uint4* d3 = (uint4*)(smB + (64 + row) * SKA + c);
#pragma unroll
            for (int i = 0; i < 4; i++) {
                d0[i] = s0[i]; d1[i] = s1[i]; d2[i] = s2[i]; d3[i] = s3[i];
            }
        }
        __syncthreads();

        if (k0t <= q0 + wm * 16 + 15) {   // warp-uniform: skip fully-masked tiles
            // ---- S = Q K^T (3-term split), f32 accum
            float s[8][4] = {};
#pragma unroll
            for (int ks = 0; ks < 4; ks++)
#pragma unroll
                for (int g = 0; g < 4; g++) {
                    u32 kh4[4], kl4[4];
                    ldmx4(kh4, kh_b + sboff + g * 16 * SKA * 2 + ks * 32);
                    ldmx4(kl4, kl_b + sboff + g * 16 * SKA * 2 + ks * 32);
                    mma_bf16(s[2 * g],     qh[ks], kh4[0], kh4[2]);
                    mma_bf16(s[2 * g],     qh[ks], kl4[0], kl4[2]);
                    mma_bf16(s[2 * g],     ql[ks], kh4[0], kh4[2]);
                    mma_bf16(s[2 * g + 1], qh[ks], kh4[1], kh4[3]);
                    mma_bf16(s[2 * g + 1], qh[ks], kl4[1], kl4[3]);
                    mma_bf16(s[2 * g + 1], ql[ks], kh4[1], kh4[3]);
                }

            // ---- causal mask (diagonal tiles only)
            if (k0t + 63 > q0 + wm * 16) {
#pragma unroll
                for (int b = 0; b < 8; b++) {
                    int cb = k0t + b * 8 + (lane & 3) * 2;
                    if (cb > rowA)         s[b][0] = -1e30f;
                    if (cb + 1 > rowA)     s[b][1] = -1e30f;
                    if (cb > rowA + 8)     s[b][2] = -1e30f;
                    if (cb + 1 > rowA + 8) s[b][3] = -1e30f;
                }
            }

            // ---- online softmax (exp2 domain; quad lanes share a row)
            float nmA = mA, nmB = mB;
#pragma unroll
            for (int b = 0; b < 8; b++) {
                nmA = fmaxf(nmA, fmaxf(s[b][0], s[b][1]));
                nmB = fmaxf(nmB, fmaxf(s[b][2], s[b][3]));
            }
            nmA = fmaxf(nmA, __shfl_xor_sync(~0u, nmA, 1));
            nmA = fmaxf(nmA, __shfl_xor_sync(~0u, nmA, 2));
            nmB = fmaxf(nmB, __shfl_xor_sync(~0u, nmB, 1));
            nmB = fmaxf(nmB, __shfl_xor_sync(~0u, nmB, 2));
            float alA = ex2f(mA - nmA), alB = ex2f(mB - nmB);
            mA = nmA; mB = nmB;
#pragma unroll
            for (int b = 0; b < 8; b++) {
                o[b][0] *= alA; o[b][1] *= alA;
                o[b][2] *= alB; o[b][3] *= alB;
            }

            // ---- P = exp2(S-m), split hi/lo, PV (3-term) per kstep
            float sumA = 0.f, sumB = 0.f;
#pragma unroll
            for (int ks = 0; ks < 4; ks++) {
                float p[8];
                p[0] = ex2f(s[2 * ks][0] - mA);     p[1] = ex2f(s[2 * ks][1] - mA);
                p[2] = ex2f(s[2 * ks][2] - mB);     p[3] = ex2f(s[2 * ks][3] - mB);
                p[4] = ex2f(s[2 * ks + 1][0] - mA); p[5] = ex2f(s[2 * ks + 1][1] - mA);
                p[6] = ex2f(s[2 * ks + 1][2] - mB); p[7] = ex2f(s[2 * ks + 1][3] - mB);
                sumA += p[0] + p[1] + p[4] + p[5];
                sumB += p[2] + p[3] + p[6] + p[7];
                float hf[8];
#pragma unroll
                for (int e = 0; e < 8; e++) hf[e] = bf16rt(p[e]);
                u32 ph4[4], pl4[4];
                ph4[0] = pkbf(hf[0], hf[1]); ph4[1] = pkbf(hf[2], hf[3]);
                ph4[2] = pkbf(hf[4], hf[5]); ph4[3] = pkbf(hf[6], hf[7]);
                pl4[0] = pkbf(p[0] - hf[0], p[1] - hf[1]);
                pl4[1] = pkbf(p[2] - hf[2], p[3] - hf[3]);
                pl4[2] = pkbf(p[4] - hf[4], p[5] - hf[5]);
                pl4[3] = pkbf(p[6] - hf[6], p[7] - hf[7]);
#pragma unroll
                for (int g = 0; g < 4; g++) {
                    u32 vh4[4], vl4[4];
                    ldmx4t(vh4, vh_b + vtoff + ks * 16 * SKA * 2 + g * 32);
                    ldmx4t(vl4, vl_b + vtoff + ks * 16 * SKA * 2 + g * 32);
                    mma_bf16(o[2 * g],     ph4, vh4[0], vh4[1]);
                    mma_bf16(o[2 * g],     ph4, vl4[0], vl4[1]);
                    mma_bf16(o[2 * g],     pl4, vh4[0], vh4[1]);
                    mma_bf16(o[2 * g + 1], ph4, vh4[2], vh4[3]);
                    mma_bf16(o[2 * g + 1], ph4, vl4[2], vl4[3]);
                    mma_bf16(o[2 * g + 1], pl4, vh4[2], vh4[3]);
                }
            }
            sumA += __shfl_xor_sync(~0u, sumA, 1);
            sumA += __shfl_xor_sync(~0u, sumA, 2);
            sumB += __shfl_xor_sync(~0u, sumB, 1);
            sumB += __shfl_xor_sync(~0u, sumB, 2);
            lA = lA * alA + sumA;
            lB = lB * alB + sumB;
        }
        __syncthreads();
    }

    // ---- write ctx as bf16 hi/lo [m][1024] for proj GEMM
    const float iA = 1.0f / lA, iB = 1.0f / lB;
    const int bb = bh >> 4, hh = bh & 15;
    const size_t m0r = (size_t)(bb * S_ + rowA) * D_ + hh * 64;
    const size_t m1r = m0r + 8 * D_;
#pragma unroll
    for (int b = 0; b < 8; b++) {
        int col = b * 8 + (lane & 3) * 2;
        float f0 = o[b][0] * iA, f1 = o[b][1] * iA;
        float f2 = o[b][2] * iB, f3 = o[b][3] * iB;
        float h0 = bf16rt(f0), h1 = bf16rt(f1), h2 = bf16rt(f2), h3 = bf16rt(f3);
        *(u32*)(g_cx_hi + m0r + col) = pkbf(h0, h1);
        *(u32*)(g_cx_lo + m0r + col) = pkbf(f0 - h0, f1 - h1);
        *(u32*)(g_cx_hi + m1r + col) = pkbf(h2, h3);
        *(u32*)(g_cx_lo + m1r + col) = pkbf(f2 - h2, f3 - h3);
    }
}

// =================================================================
// LayerNorm over last dim (1024)
// =================================================================
__global__ __launch_bounds__(256) void ln_kernel(
    const float* __restrict__ gamma,
    const float* __restrict__ beta,
    float* __restrict__ out)
{
    __shared__ float ws[8], wq2[8];
    const int row = blockIdx.x;
    const int t = threadIdx.x;
    const int lane = t & 31, w = t >> 5;
    const float* rp = g_res + (size_t)row * D_;

    float4 v = *(const float4*)(rp + t * 4);
    float s = v.x + v.y + v.z + v.w;
    float q = v.x * v.x + v.y * v.y + v.z * v.z + v.w * v.w;
#pragma unroll
    for (int o = 16; o > 0; o >>= 1) {
        s += __shfl_xor_sync(0xffffffffu, s, o);
        q += __shfl_xor_sync(0xffffffffu, q, o);
    }
    if (lane == 0) { ws[w] = s; wq2[w] = q; }
    __syncthreads();
    float S = 0.f, Q = 0.f;
#pragma unroll
    for (int i = 0; i < 8; i++) { S += ws[i]; Q += wq2[i]; }

    float mu  = S * (1.0f / 1024.0f);
    float var = Q * (1.0f / 1024.0f) - mu * mu;
    float rstd = rsqrtf(var + 1e-5f);

    float4 g  = *(const float4*)(gamma + t * 4);
    float4 bt = *(const float4*)(beta  + t * 4);
    float4 o4;
    o4.x = (v.x - mu) * rstd * g.x + bt.x;
    o4.y = (v.y - mu) * rstd * g.y + bt.y;
    o4.z = (v.z - mu) * rstd * g.z + bt.z;
    o4.w = (v.w - mu) * rstd * g.w + bt.w;
    *(float4*)(out + (size_t)row * D_ + t * 4) = o4;
}

// =================================================================
extern "C" void kernel_launch(void* const* d_in, const int* in_sizes, int n_in,
                              void* d_out, int out_size)
{
    const float* x     = (const float*)d_in[0];
    const float* wq    = (const float*)d_in[1];
    const float* wk    = (const float*)d_in[2];
    const float* wv    = (const float*)d_in[3];
    const float* wo    = (const float*)d_in[4];
    const float* gamma = (const float*)d_in[5];
    const float* beta  = (const float*)d_in[6];
    float* out = (float*)d_out;

    const int gemm_smem = 2 * STAGE_BYTES;   // 80 KB double-buffered
    cudaFuncSetAttribute(qkv_hmma,
                         cudaFuncAttributeMaxDynamicSharedMemorySize, gemm_smem);
    cudaFuncSetAttribute(proj_hmma,
                         cudaFuncAttributeMaxDynamicSharedMemorySize, gemm_smem);

    split_x<<<M_, 256>>>(x);
    wt_split<<<dim3(32, 128), dim3(32, 8)>>>(wq, wk, wv, wo);
    qkv_hmma<<<dim3(M_ / 128, 3072 / 128), 256, gemm_smem>>>();
    attn_hmma<<<dim3(S_ / 64, B_ * H_), 128>>>();
    proj_hmma<<<dim3(M_ / 128, D_ / 128), 256, gemm_smem>>>(x);
    ln_kernel<<<M_, 256>>>(gamma, beta, out);
}